// round 7
// baseline (speedup 1.0000x reference)
#include <cuda_runtime.h>
#include <math.h>
#include <stdint.h>

#define BN 8
#define C 256
#define HWn 4096
#define KFULL 2304

// ---------------- scratch (device globals: allocation-free) ----------------
__device__ float g_xt [(size_t)BN*HWn*C];        // x NHWC, tf32-rounded
__device__ float g_y1h[(size_t)BN*HWn*C];        // conv1 NHWC raw -> (in place) bn+relu rounded
__device__ float g_d2 [(size_t)BN*C*HWn];        // deform conv raw NCHW
__device__ float g_res[(size_t)BN*C*HWn];        // 1x1 raw NCHW
__device__ float g_off[BN*18*HWn];
__device__ float g_mask[BN*9*HWn];
__device__ float g_taps[(size_t)BN*HWn*9*8];     // per (b,pix,p): w00..w11, o00..o11(premul 256)
__device__ float g_stats[6*256];
__device__ float g_ps[3*256*256];
__device__ float g_pq[3*256*256];
__device__ float g_w1p[256*KFULL];               // w1  -> [co][t*256+ci] rounded
__device__ float g_wdp[256*KFULL];               // w_d -> [co][t*256+ci] rounded
__device__ float g_wop[32*KFULL];                // off+mod packed (27 rows + 5 zero)
__device__ float g_wds[256*256];                 // w_ds rounded
__device__ float g_bp[32];

// ---------------- helpers -----------------------------------------------------
__device__ __forceinline__ unsigned f2tf(float v) {
    unsigned u; asm("cvt.rna.tf32.f32 %0, %1;" : "=r"(u) : "f"(v)); return u;
}
__device__ __forceinline__ float f2tff(float v) { return __uint_as_float(f2tf(v)); }
__device__ __forceinline__ uint32_t s2u(const void* p) {
    uint32_t a;
    asm("{ .reg .u64 t; cvta.to.shared.u64 t, %1; cvt.u32.u64 %0, t; }" : "=r"(a) : "l"(p));
    return a;
}
__device__ __forceinline__ void cpa16(uint32_t dst, const void* src, bool v) {
    int sz = v ? 16 : 0;
    asm volatile("cp.async.cg.shared.global [%0], [%1], 16, %2;"
                 :: "r"(dst), "l"(src), "r"(sz) : "memory");
}
__device__ __forceinline__ void mma8(float* d, const uint4& a, const uint2& b) {
    asm volatile("mma.sync.aligned.m16n8k8.row.col.f32.tf32.tf32.f32 "
        "{%0,%1,%2,%3}, {%4,%5,%6,%7}, {%8,%9}, {%0,%1,%2,%3};"
        : "+f"(d[0]), "+f"(d[1]), "+f"(d[2]), "+f"(d[3])
        : "r"(a.x), "r"(a.y), "r"(a.z), "r"(a.w), "r"(b.x), "r"(b.y));
}

// ---------------- unified tf32 GEMM ---------------------------------------------
// D[M co x 128 pix] = A[co][k] * B[k][pix], K chunks of 32, 256 threads.
// BMODE 0: B[k][pix] = Bm[(b*4096+pix)*ROWLEN + k]   (cp.async)
// BMODE 1: implicit 3x3 im2col of NHWC Bm, k = t*256+ci   (cp.async, zero-fill)
// BMODE 2: deformable gather: Bm = NHWC src, taps give corners+weights (sync LDG)
// EPI 0: NCHW out (+bias).  EPI 1: NHWC out (+bias).  EPI 2: offsets/mask.
// STATS: emit per-channel partial sum/sumsq -> ps/pq[(co)*256 + cta].
template<int M, int BMODE, int EPI, bool STATS>
__global__ void __launch_bounds__(256, 2) gemm_v4(
    const float* __restrict__ A, const float* __restrict__ Bm,
    const float* __restrict__ bias,
    float* __restrict__ out0, float* __restrict__ out1,
    const float* __restrict__ taps,
    float* __restrict__ ps, float* __restrict__ pq,
    int Kdim, int ROWLEN)
{
    constexpr int WN = 256 / M;
    constexpr int NT = M / 16;
    constexpr int APITCH = 36;
    constexpr int ABUF = M * APITCH;
    constexpr int BBUF = 128 * APITCH;
    constexpr int STAGE = ABUF + BBUF;

    extern __shared__ float sm[];
    const int tid = threadIdx.x, lane = tid & 31, warp = tid >> 5;
    const int wm = warp / WN, wn = warp % WN;
    const int g = lane >> 2, tig = lane & 3;
    const int pix0 = blockIdx.x * 128, co0 = blockIdx.y * M, b = blockIdx.z;
    const int cta = blockIdx.x + (blockIdx.z << 5);
    const uint32_t smu = s2u(sm);

    float acc[2][NT][4] = {};
    const int nch = Kdim >> 5;

    auto stage = [&](int ic, int buf) {
        const int k0 = ic << 5;
        uint32_t sA = smu + buf * STAGE * 4;
        uint32_t sB = sA + ABUF * 4;
        #pragma unroll
        for (int i = 0; i < M/32; i++) {            // A: M x 32k via cp.async
            int idx = tid + i*256;
            int row = idx >> 3, kq = idx & 7;
            cpa16(sA + (row*APITCH + kq*4)*4,
                  A + (size_t)(co0+row)*Kdim + k0 + kq*4, true);
        }
        if (BMODE == 2) {
            const int p = k0 >> 8, ci0 = k0 & 255;
            float* sBf = sm + buf*STAGE + ABUF;
            const float* base = Bm + (size_t)b*4096*256 + ci0;
            #pragma unroll
            for (int i = 0; i < 4; i++) {
                int idx = tid + i*256;
                int pp = idx >> 3, kq = idx & 7;
                const float* tp = taps + ((size_t)(b*4096 + pix0+pp)*9 + p)*8;
                const float4 w = *(const float4*)tp;
                const int4  o = *(const int4*)(tp + 4);
                const float* bb = base + kq*4;
                const float4 c00 = *(const float4*)(bb + o.x);
                const float4 c01 = *(const float4*)(bb + o.y);
                const float4 c10 = *(const float4*)(bb + o.z);
                const float4 c11 = *(const float4*)(bb + o.w);
                float4 r;
                r.x = w.x*c00.x + w.y*c01.x + w.z*c10.x + w.w*c11.x;
                r.y = w.x*c00.y + w.y*c01.y + w.z*c10.y + w.w*c11.y;
                r.z = w.x*c00.z + w.y*c01.z + w.z*c10.z + w.w*c11.z;
                r.w = w.x*c00.w + w.y*c01.w + w.z*c10.w + w.w*c11.w;
                *(float4*)&sBf[pp*APITCH + kq*4] = r;
            }
        } else {
            int ty = 0, tx = 0, ci0 = 0;
            if (BMODE == 1) { int t = k0 >> 8; ty = t/3 - 1; tx = t%3 - 1; ci0 = k0 & 255; }
            #pragma unroll
            for (int i = 0; i < 4; i++) {
                int idx = tid + i*256;
                int pp = idx >> 3, kq = idx & 7;
                uint32_t dst = sB + (pp*APITCH + kq*4)*4;
                if (BMODE == 1) {
                    int pix = pix0 + pp;
                    int py = (pix >> 6) + ty, px = (pix & 63) + tx;
                    bool v = (py >= 0) && (py < 64) && (px >= 0) && (px < 64);
                    cpa16(dst, Bm + ((size_t)b*4096 + (v ? (py*64+px) : 0))*256
                               + ci0 + kq*4, v);
                } else {
                    cpa16(dst, Bm + ((size_t)b*4096 + pix0 + pp)*(size_t)ROWLEN
                               + k0 + kq*4, true);
                }
            }
        }
        asm volatile("cp.async.commit_group;" ::: "memory");
    };

    stage(0, 0);
    for (int ic = 0; ic < nch; ic++) {
        const int buf = ic & 1;
        if (ic + 1 < nch) {
            stage(ic + 1, buf ^ 1);
            asm volatile("cp.async.wait_group 1;" ::: "memory");
        } else {
            asm volatile("cp.async.wait_group 0;" ::: "memory");
        }
        __syncthreads();
        const float* sA = sm + buf*STAGE;
        const float* sB = sA + ABUF;
        #pragma unroll
        for (int k8 = 0; k8 < 4; k8++) {
            const int kb = k8 * 8;
            uint4 af[2];
            #pragma unroll
            for (int m = 0; m < 2; m++) {
                const int cw = wm*32 + m*16;
                af[m].x = __float_as_uint(sA[(cw+g  )*APITCH + kb+tig  ]);
                af[m].y = __float_as_uint(sA[(cw+g+8)*APITCH + kb+tig  ]);
                af[m].z = __float_as_uint(sA[(cw+g  )*APITCH + kb+tig+4]);
                af[m].w = __float_as_uint(sA[(cw+g+8)*APITCH + kb+tig+4]);
            }
            #pragma unroll
            for (int nn = 0; nn < NT; nn++) {
                const int pc = wn*(NT*8) + nn*8 + g;
                uint2 bb;
                bb.x = __float_as_uint(sB[pc*APITCH + kb+tig  ]);
                bb.y = __float_as_uint(sB[pc*APITCH + kb+tig+4]);
                mma8(acc[0][nn], af[0], bb);
                mma8(acc[1][nn], af[1], bb);
            }
        }
        __syncthreads();
    }

    // ---- epilogue (reuses smem) ----
    float* sE = sm;
    if (EPI == 0) {                            // NCHW out, bias at fill
        #pragma unroll
        for (int p = 0; p < M/32; p++) {
            if (wm == p) {
                #pragma unroll
                for (int m = 0; m < 2; m++) {
                    const int r = m*16 + g;
                    const float b0 = bias[co0 + p*32 + r];
                    const float b1 = bias[co0 + p*32 + r + 8];
                    #pragma unroll
                    for (int nn = 0; nn < NT; nn++) {
                        const int pl = wn*(NT*8) + nn*8 + tig*2;
                        sE[r*132 + pl]       = acc[m][nn][0] + b0;
                        sE[r*132 + pl+1]     = acc[m][nn][1] + b0;
                        sE[(r+8)*132 + pl]   = acc[m][nn][2] + b1;
                        sE[(r+8)*132 + pl+1] = acc[m][nn][3] + b1;
                    }
                }
            }
            __syncthreads();
            #pragma unroll
            for (int i = 0; i < 4; i++) {
                int idx = tid + i*256;
                int r = idx >> 5, p4 = idx & 31;
                float4 v = *(float4*)&sE[r*132 + p4*4];
                *(float4*)(out0 + (((size_t)b*256 + co0 + p*32 + r) << 12)
                           + pix0 + p4*4) = v;
                if (STATS) {
                    float s  = v.x + v.y + v.z + v.w;
                    float s2 = v.x*v.x + v.y*v.y + v.z*v.z + v.w*v.w;
                    #pragma unroll
                    for (int o = 16; o > 0; o >>= 1) {
                        s  += __shfl_xor_sync(0xffffffffu, s,  o);
                        s2 += __shfl_xor_sync(0xffffffffu, s2, o);
                    }
                    if (lane == 0) {
                        ps[(co0 + p*32 + r)*256 + cta] = s;
                        pq[(co0 + p*32 + r)*256 + cta] = s2;
                    }
                }
            }
            __syncthreads();
        }
    } else if (EPI == 1) {                     // NHWC out (M=128, WN=2)
        float sc = 0.f, sc2 = 0.f;
        #pragma unroll
        for (int pass = 0; pass < 2; pass++) {
            if (wn == pass) {
                #pragma unroll
                for (int m = 0; m < 2; m++) {
                    const int r0 = wm*32 + m*16 + g;
                    const float b0 = bias[co0 + r0], b1 = bias[co0 + r0 + 8];
                    #pragma unroll
                    for (int nn = 0; nn < NT; nn++) {
                        const int pl = nn*8 + tig*2;
                        sE[pl*132 + r0]       = acc[m][nn][0] + b0;
                        sE[(pl+1)*132 + r0]   = acc[m][nn][1] + b0;
                        sE[pl*132 + r0+8]     = acc[m][nn][2] + b1;
                        sE[(pl+1)*132 + r0+8] = acc[m][nn][3] + b1;
                    }
                }
            }
            __syncthreads();
            #pragma unroll
            for (int i = 0; i < 8; i++) {
                int idx = tid + i*256;
                int pp = idx >> 5, c4 = idx & 31;
                float4 v = *(float4*)&sE[pp*132 + c4*4];
                *(float4*)(out0 + ((size_t)b*4096 + pix0 + pass*64 + pp)*256
                           + co0 + c4*4) = v;
            }
            if (STATS && tid < 128) {
                for (int pp = 0; pp < 64; pp++) {
                    float v = sE[pp*132 + tid];
                    sc += v; sc2 += v*v;
                }
            }
            __syncthreads();
        }
        if (STATS && tid < 128) {
            ps[(co0 + tid)*256 + cta] = sc;
            pq[(co0 + tid)*256 + cta] = sc2;
        }
    } else {                                   // EPI 2: offsets + mask (M=32)
        #pragma unroll
        for (int m = 0; m < 2; m++)
            #pragma unroll
            for (int nn = 0; nn < NT; nn++) {
                const int r = m*16 + g;
                const int pl = wn*(NT*8) + nn*8 + tig*2;
                sE[r*132 + pl]       = acc[m][nn][0];
                sE[r*132 + pl+1]     = acc[m][nn][1];
                sE[(r+8)*132 + pl]   = acc[m][nn][2];
                sE[(r+8)*132 + pl+1] = acc[m][nn][3];
            }
        __syncthreads();
        if (tid < 128) {
            const int pix = pix0 + tid;
            #pragma unroll
            for (int r = 0; r < 27; r++) {
                float v = sE[r*132 + tid] + bias[r];
                if (r < 18) out0[((size_t)b*18 + r)*4096 + pix] = v;
                else        out1[((size_t)b*9 + r - 18)*4096 + pix] = 2.f/(1.f + expf(-v));
            }
        }
    }
}

// ---------------- stats combine: 256 partials -> mean/rstd ---------------------
__global__ __launch_bounds__(256) void bn_combine(const float* __restrict__ ps,
    const float* __restrict__ pq, float* __restrict__ st)
{
    const int c = threadIdx.x;
    float s = 0.f, s2 = 0.f;
    for (int j = 0; j < 256; j++) { s += ps[c*256 + j]; s2 += pq[c*256 + j]; }
    const float m = s * (1.f/32768.f);
    const float var = s2 * (1.f/32768.f) - m*m;
    st[c] = m;
    st[256 + c] = rsqrtf(var + 1e-5f);
}

// ---------------- tap prep: bilinear weights + corner offsets ------------------
__global__ __launch_bounds__(256) void tap_prep(const float* __restrict__ off,
    const float* __restrict__ msk, float* __restrict__ taps)
{
    const int i = blockIdx.x*256 + threadIdx.x;     // over BN*9*HWn
    const int pix = i & 4095;
    const int r = i >> 12;
    const int b = r / 9, p = r - b*9;
    const int ho = pix >> 6, wo = pix & 63;

    const float dy = off[((size_t)b*18 + 2*p    )*4096 + pix];
    const float dx = off[((size_t)b*18 + 2*p + 1)*4096 + pix];
    const float m  = msk[((size_t)b*9 + p)*4096 + pix];
    const float py = (float)(ho - 1 + p/3) + dy;
    const float px = (float)(wo - 1 + p%3) + dx;

    const float y0f = floorf(py), x0f = floorf(px);
    const float ly = py - y0f, lx = px - x0f;
    const int y0 = (int)y0f, x0 = (int)x0f;
    const int y1 = y0 + 1,  x1 = x0 + 1;
    float w00 = (1.f-ly)*(1.f-lx), w01 = (1.f-ly)*lx, w10 = ly*(1.f-lx), w11 = ly*lx;
    const bool vy0 = (y0 >= 0) && (y0 < 64), vy1 = (y1 >= 0) && (y1 < 64);
    const bool vx0 = (x0 >= 0) && (x0 < 64), vx1 = (x1 >= 0) && (x1 < 64);
    if (!(vy0 && vx0)) w00 = 0.f;
    if (!(vy0 && vx1)) w01 = 0.f;
    if (!(vy1 && vx0)) w10 = 0.f;
    if (!(vy1 && vx1)) w11 = 0.f;
    const int yc0 = min(max(y0, 0), 63), yc1 = min(max(y1, 0), 63);
    const int xc0 = min(max(x0, 0), 63), xc1 = min(max(x1, 0), 63);

    float4 w = make_float4(w00*m, w01*m, w10*m, w11*m);
    int4 o = make_int4((yc0*64 + xc0)*256, (yc0*64 + xc1)*256,
                       (yc1*64 + xc0)*256, (yc1*64 + xc1)*256);
    float* tp = taps + ((size_t)(b*4096 + pix)*9 + p)*8;
    *(float4*)tp = w;
    *(int4*)(tp + 4) = o;
}

// ---------------- prep kernels ---------------------------------------------------
__global__ __launch_bounds__(256) void permuteK_round(const float* __restrict__ in,
                                                      float* __restrict__ out)
{
    int i = blockIdx.x*256 + threadIdx.x;
    int co = i / KFULL, r = i - co*KFULL;
    int t = r >> 8, ci = r & 255;
    out[i] = f2tff(in[co*KFULL + ci*9 + t]);
}

__global__ __launch_bounds__(256) void pack_offmod_round(
    const float* __restrict__ w_off, const float* __restrict__ w_mod,
    const float* __restrict__ b_off, const float* __restrict__ b_mod,
    float* __restrict__ wp, float* __restrict__ bp)
{
    int i = blockIdx.x*256 + threadIdx.x;
    if (i < 32*KFULL) {
        int o = i / KFULL, r = i - o*KFULL;
        int t = r >> 8, ci = r & 255;
        float v = 0.f;
        if (o < 18)      v = w_off[o*KFULL + ci*9 + t];
        else if (o < 27) v = w_mod[(o-18)*KFULL + ci*9 + t];
        wp[i] = f2tff(v);
    }
    if (i < 27) bp[i] = (i < 18) ? b_off[i] : b_mod[i-18];
}

__global__ __launch_bounds__(256) void round_wds(const float* __restrict__ in,
                                                 float* __restrict__ out)
{
    int i = blockIdx.x*256 + threadIdx.x;
    out[i] = f2tff(in[i]);
}

// NCHW -> NHWC tf32-rounded (for x)
__global__ __launch_bounds__(256) void nhwc_round(const float* __restrict__ in,
                                                  float* __restrict__ out)
{
    __shared__ float tb[32][33];
    const int pix0 = blockIdx.x*32, c0 = blockIdx.y*32, b = blockIdx.z;
    const int tx = threadIdx.x & 31, ty = threadIdx.x >> 5;
    #pragma unroll
    for (int i = 0; i < 4; i++)
        tb[ty + i*8][tx] = f2tff(in[((size_t)b*256 + c0 + ty + i*8)*4096 + pix0 + tx]);
    __syncthreads();
    #pragma unroll
    for (int i = 0; i < 4; i++)
        out[((size_t)b*4096 + pix0 + ty + i*8)*256 + c0 + tx] = tb[tx][ty + i*8];
}

// in-place BN + ReLU + tf32 round on NHWC
__global__ __launch_bounds__(256) void bn_relu_nhwc(float* __restrict__ y,
    const float* __restrict__ st, const float* __restrict__ g, const float* __restrict__ bt)
{
    const int i = blockIdx.x*256 + threadIdx.x;
    const int c = i & 255;
    const float v = (y[i] - st[c]) * st[256 + c] * g[c] + bt[c];
    y[i] = f2tff(fmaxf(v, 0.f));
}

// ---------------- final: relu( bn2(d2) + bn3(res) ) ------------------------------
__global__ __launch_bounds__(256) void final_fuse(
    const float* __restrict__ d2, const float* __restrict__ res,
    const float* __restrict__ st,
    const float* __restrict__ g2, const float* __restrict__ bt2,
    const float* __restrict__ g3, const float* __restrict__ bt3,
    float* __restrict__ out)
{
    const int i = blockIdx.x*256 + threadIdx.x;
    const int c = (i >> 12) & 255;
    const float a = (d2[i]  - st[512 + c])  * st[768 + c]  * g2[c] + bt2[c];
    const float r = (res[i] - st[1024 + c]) * st[1280 + c] * g3[c] + bt3[c];
    out[i] = fmaxf(a + r, 0.f);
}

// ---------------- launcher ---------------------------------------------------------
extern "C" void kernel_launch(void* const* d_in, const int* in_sizes, int n_in,
                              void* d_out, int out_size)
{
    const float* x     = (const float*)d_in[0];
    const float* w1    = (const float*)d_in[2];
    const float* b1    = (const float*)d_in[3];
    const float* g1    = (const float*)d_in[4];
    const float* bt1   = (const float*)d_in[5];
    const float* w_off = (const float*)d_in[6];
    const float* b_off = (const float*)d_in[7];
    const float* w_mod = (const float*)d_in[8];
    const float* b_mod = (const float*)d_in[9];
    const float* w_d   = (const float*)d_in[10];
    const float* b_d   = (const float*)d_in[11];
    const float* g2    = (const float*)d_in[12];
    const float* bt2   = (const float*)d_in[13];
    const float* w_ds  = (const float*)d_in[14];
    const float* b_ds  = (const float*)d_in[15];
    const float* g3    = (const float*)d_in[16];
    const float* bt3   = (const float*)d_in[17];

    float *xt, *y1h, *d2, *res, *off, *msk, *taps, *st, *ps, *pq;
    float *w1p, *wdp, *wop, *wds, *bp;
    cudaGetSymbolAddress((void**)&xt,   g_xt);
    cudaGetSymbolAddress((void**)&y1h,  g_y1h);
    cudaGetSymbolAddress((void**)&d2,   g_d2);
    cudaGetSymbolAddress((void**)&res,  g_res);
    cudaGetSymbolAddress((void**)&off,  g_off);
    cudaGetSymbolAddress((void**)&msk,  g_mask);
    cudaGetSymbolAddress((void**)&taps, g_taps);
    cudaGetSymbolAddress((void**)&st,   g_stats);
    cudaGetSymbolAddress((void**)&ps,   g_ps);
    cudaGetSymbolAddress((void**)&pq,   g_pq);
    cudaGetSymbolAddress((void**)&w1p,  g_w1p);
    cudaGetSymbolAddress((void**)&wdp,  g_wdp);
    cudaGetSymbolAddress((void**)&wop,  g_wop);
    cudaGetSymbolAddress((void**)&wds,  g_wds);
    cudaGetSymbolAddress((void**)&bp,   g_bp);

    const int SM128 = 2 * (128*36 + 128*36) * 4;   // 73728
    const int SM32  = 2 * (32*36  + 128*36) * 4;   // 46080
    cudaFuncSetAttribute(gemm_v4<128,1,1,true>,  cudaFuncAttributeMaxDynamicSharedMemorySize, SM128);
    cudaFuncSetAttribute(gemm_v4<128,2,0,true>,  cudaFuncAttributeMaxDynamicSharedMemorySize, SM128);
    cudaFuncSetAttribute(gemm_v4<128,0,0,true>,  cudaFuncAttributeMaxDynamicSharedMemorySize, SM128);
    cudaFuncSetAttribute(gemm_v4<32,1,2,false>,  cudaFuncAttributeMaxDynamicSharedMemorySize, SM32);

    // 0) prep
    nhwc_round<<<dim3(128, 8, BN), 256>>>(x, xt);
    permuteK_round<<<256*KFULL/256, 256>>>(w1,  w1p);
    permuteK_round<<<256*KFULL/256, 256>>>(w_d, wdp);
    pack_offmod_round<<<32*KFULL/256, 256>>>(w_off, w_mod, b_off, b_mod, wop, bp);
    round_wds<<<256*256/256, 256>>>(w_ds, wds);

    // 1) conv1: implicit 3x3 GEMM -> y1h NHWC raw + stats partials
    gemm_v4<128,1,1,true><<<dim3(32, 2, BN), 256, SM128>>>(
        w1p, xt, b1, y1h, nullptr, nullptr, ps, pq, KFULL, 0);
    bn_combine<<<1, 256>>>(ps, pq, st);
    // 2) BN1 + ReLU + round, in place
    bn_relu_nhwc<<<(int)((size_t)BN*HWn*C/256), 256>>>(y1h, st, g1, bt1);
    // 3) offsets + modulation
    gemm_v4<32,1,2,false><<<dim3(32, 1, BN), 256, SM32>>>(
        wop, y1h, bp, off, msk, nullptr, nullptr, nullptr, KFULL, 0);
    // 4) bilinear tap prep (weights + corner offsets only)
    tap_prep<<<BN*9*HWn/256, 256>>>(off, msk, taps);
    // 5) deformable GEMM with fused gather -> d2 NCHW + stats
    gemm_v4<128,2,0,true><<<dim3(32, 2, BN), 256, SM128>>>(
        wdp, y1h, b_d, d2, nullptr, taps, ps + 65536, pq + 65536, KFULL, 0);
    // 6) 1x1 shortcut -> res NCHW + stats
    gemm_v4<128,0,0,true><<<dim3(32, 2, BN), 256, SM128>>>(
        wds, xt, b_ds, res, nullptr, nullptr, ps + 2*65536, pq + 2*65536, 256, 256);
    bn_combine<<<1, 256>>>(ps + 65536,   pq + 65536,   st + 512);
    bn_combine<<<1, 256>>>(ps + 2*65536, pq + 2*65536, st + 1024);
    // 7) fused BN2 + BN3 + add + ReLU
    final_fuse<<<BN*C*HWn/256, 256>>>(d2, res, st, g2, bt2, g3, bt3, (float*)d_out);
}

// round 8
// speedup vs baseline: 1.0340x; 1.0340x over previous
#include <cuda_runtime.h>
#include <math.h>
#include <stdint.h>

#define BN 8
#define C 256
#define HWn 4096
#define KFULL 2304

// ---------------- scratch (device globals: allocation-free) ----------------
__device__ float g_xt [(size_t)BN*HWn*C];        // x NHWC, tf32-rounded
__device__ float g_y1h[(size_t)BN*HWn*C];        // conv1 NHWC raw -> (in place) bn+relu rounded
__device__ float g_d2 [(size_t)BN*C*HWn];        // deform conv raw NCHW
__device__ float g_res[(size_t)BN*C*HWn];        // 1x1 raw NCHW
__device__ float g_off[BN*18*HWn];
__device__ float g_mask[BN*9*HWn];
__device__ float g_col[(size_t)BN*HWn*KFULL];    // [b][pix][k=p*256+ci], rounded
__device__ float g_stats[6*256];
__device__ float g_ps[3*256*256];
__device__ float g_pq[3*256*256];
__device__ float g_w1p[256*KFULL];               // w1  -> [co][t*256+ci] rounded
__device__ float g_wdp[256*KFULL];               // w_d -> [co][t*256+ci] rounded
__device__ float g_wop[32*KFULL];                // off+mod packed (27 rows + 5 zero)
__device__ float g_wds[256*256];                 // w_ds rounded
__device__ float g_bp[32];

// ---------------- helpers -----------------------------------------------------
__device__ __forceinline__ unsigned f2tf(float v) {
    unsigned u; asm("cvt.rna.tf32.f32 %0, %1;" : "=r"(u) : "f"(v)); return u;
}
__device__ __forceinline__ float f2tff(float v) { return __uint_as_float(f2tf(v)); }
__device__ __forceinline__ uint32_t s2u(const void* p) {
    uint32_t a;
    asm("{ .reg .u64 t; cvta.to.shared.u64 t, %1; cvt.u32.u64 %0, t; }" : "=r"(a) : "l"(p));
    return a;
}
__device__ __forceinline__ void cpa16(uint32_t dst, const void* src, bool v) {
    int sz = v ? 16 : 0;
    asm volatile("cp.async.cg.shared.global [%0], [%1], 16, %2;"
                 :: "r"(dst), "l"(src), "r"(sz) : "memory");
}
__device__ __forceinline__ void mma8(float* d, const uint4& a, const uint2& b) {
    asm volatile("mma.sync.aligned.m16n8k8.row.col.f32.tf32.tf32.f32 "
        "{%0,%1,%2,%3}, {%4,%5,%6,%7}, {%8,%9}, {%0,%1,%2,%3};"
        : "+f"(d[0]), "+f"(d[1]), "+f"(d[2]), "+f"(d[3])
        : "r"(a.x), "r"(a.y), "r"(a.z), "r"(a.w), "r"(b.x), "r"(b.y));
}

// ---------------- unified tf32 GEMM, cp.async double-buffered -------------------
// D[M co x 128 pix] = A[co][k] * B[k][pix], K chunks of 32, 256 threads.
// BMODE 0: B[k][pix] = Bm[(b*4096+pix)*ROWLEN + k]
// BMODE 1: implicit 3x3 im2col of NHWC Bm, k = t*256+ci (zero-fill via cp.async)
// EPI 0: NCHW out (+bias).  EPI 1: NHWC out (+bias).  EPI 2: offsets/mask.
// STATS: per-channel partial sum/sumsq -> ps/pq[c*256 + cta].
template<int M, int BMODE, int EPI, bool STATS>
__global__ void __launch_bounds__(256, 2) gemm_v4(
    const float* __restrict__ A, const float* __restrict__ Bm,
    const float* __restrict__ bias,
    float* __restrict__ out0, float* __restrict__ out1,
    float* __restrict__ ps, float* __restrict__ pq,
    int Kdim, int ROWLEN)
{
    constexpr int WN = 256 / M;
    constexpr int NT = M / 16;
    constexpr int APITCH = 36;
    constexpr int ABUF = M * APITCH;
    constexpr int BBUF = 128 * APITCH;
    constexpr int STAGE = ABUF + BBUF;

    extern __shared__ float sm[];
    const int tid = threadIdx.x, lane = tid & 31, warp = tid >> 5;
    const int wm = warp / WN, wn = warp % WN;
    const int g = lane >> 2, tig = lane & 3;
    const int pix0 = blockIdx.x * 128, co0 = blockIdx.y * M, b = blockIdx.z;
    const int cta = blockIdx.x + (blockIdx.z << 5);
    const uint32_t smu = s2u(sm);

    float acc[2][NT][4] = {};
    const int nch = Kdim >> 5;

    auto stage = [&](int ic, int buf) {
        const int k0 = ic << 5;
        uint32_t sA = smu + buf * STAGE * 4;
        uint32_t sB = sA + ABUF * 4;
        #pragma unroll
        for (int i = 0; i < M/32; i++) {            // A: M x 32k
            int idx = tid + i*256;
            int row = idx >> 3, kq = idx & 7;
            cpa16(sA + (row*APITCH + kq*4)*4,
                  A + (size_t)(co0+row)*Kdim + k0 + kq*4, true);
        }
        int ty = 0, tx = 0, ci0 = 0;
        if (BMODE == 1) { int t = k0 >> 8; ty = t/3 - 1; tx = t%3 - 1; ci0 = k0 & 255; }
        #pragma unroll
        for (int i = 0; i < 4; i++) {               // B: 32k x 128pix
            int idx = tid + i*256;
            int pp = idx >> 3, kq = idx & 7;
            uint32_t dst = sB + (pp*APITCH + kq*4)*4;
            if (BMODE == 1) {
                int pix = pix0 + pp;
                int py = (pix >> 6) + ty, px = (pix & 63) + tx;
                bool v = (py >= 0) && (py < 64) && (px >= 0) && (px < 64);
                cpa16(dst, Bm + ((size_t)b*4096 + (v ? (py*64+px) : 0))*256
                           + ci0 + kq*4, v);
            } else {
                cpa16(dst, Bm + ((size_t)b*4096 + pix0 + pp)*(size_t)ROWLEN
                           + k0 + kq*4, true);
            }
        }
        asm volatile("cp.async.commit_group;" ::: "memory");
    };

    stage(0, 0);
    for (int ic = 0; ic < nch; ic++) {
        const int buf = ic & 1;
        if (ic + 1 < nch) {
            stage(ic + 1, buf ^ 1);
            asm volatile("cp.async.wait_group 1;" ::: "memory");
        } else {
            asm volatile("cp.async.wait_group 0;" ::: "memory");
        }
        __syncthreads();
        const float* sA = sm + buf*STAGE;
        const float* sB = sA + ABUF;
        #pragma unroll
        for (int k8 = 0; k8 < 4; k8++) {
            const int kb = k8 * 8;
            uint4 af[2];
            #pragma unroll
            for (int m = 0; m < 2; m++) {
                const int cw = wm*32 + m*16;
                af[m].x = __float_as_uint(sA[(cw+g  )*APITCH + kb+tig  ]);
                af[m].y = __float_as_uint(sA[(cw+g+8)*APITCH + kb+tig  ]);
                af[m].z = __float_as_uint(sA[(cw+g  )*APITCH + kb+tig+4]);
                af[m].w = __float_as_uint(sA[(cw+g+8)*APITCH + kb+tig+4]);
            }
            #pragma unroll
            for (int nn = 0; nn < NT; nn++) {
                const int pc = wn*(NT*8) + nn*8 + g;
                uint2 bb;
                bb.x = __float_as_uint(sB[pc*APITCH + kb+tig  ]);
                bb.y = __float_as_uint(sB[pc*APITCH + kb+tig+4]);
                mma8(acc[0][nn], af[0], bb);
                mma8(acc[1][nn], af[1], bb);
            }
        }
        __syncthreads();
    }

    // ---- epilogue (reuses smem) ----
    float* sE = sm;
    if (EPI == 0) {                            // NCHW out, bias at fill, opt stats
        #pragma unroll
        for (int p = 0; p < M/32; p++) {
            if (wm == p) {
                #pragma unroll
                for (int m = 0; m < 2; m++) {
                    const int r = m*16 + g;
                    const float b0 = bias[co0 + p*32 + r];
                    const float b1 = bias[co0 + p*32 + r + 8];
                    #pragma unroll
                    for (int nn = 0; nn < NT; nn++) {
                        const int pl = wn*(NT*8) + nn*8 + tig*2;
                        sE[r*132 + pl]       = acc[m][nn][0] + b0;
                        sE[r*132 + pl+1]     = acc[m][nn][1] + b0;
                        sE[(r+8)*132 + pl]   = acc[m][nn][2] + b1;
                        sE[(r+8)*132 + pl+1] = acc[m][nn][3] + b1;
                    }
                }
            }
            __syncthreads();
            #pragma unroll
            for (int i = 0; i < 4; i++) {
                int idx = tid + i*256;
                int r = idx >> 5, p4 = idx & 31;
                float4 v = *(float4*)&sE[r*132 + p4*4];
                *(float4*)(out0 + (((size_t)b*256 + co0 + p*32 + r) << 12)
                           + pix0 + p4*4) = v;
                if (STATS) {
                    float s  = v.x + v.y + v.z + v.w;
                    float s2 = v.x*v.x + v.y*v.y + v.z*v.z + v.w*v.w;
                    #pragma unroll
                    for (int o = 16; o > 0; o >>= 1) {
                        s  += __shfl_xor_sync(0xffffffffu, s,  o);
                        s2 += __shfl_xor_sync(0xffffffffu, s2, o);
                    }
                    if (lane == 0) {
                        ps[(co0 + p*32 + r)*256 + cta] = s;
                        pq[(co0 + p*32 + r)*256 + cta] = s2;
                    }
                }
            }
            __syncthreads();
        }
    } else if (EPI == 1) {                     // NHWC out (M=128, WN=2), opt stats
        float sc = 0.f, sc2 = 0.f;
        #pragma unroll
        for (int pass = 0; pass < 2; pass++) {
            if (wn == pass) {
                #pragma unroll
                for (int m = 0; m < 2; m++) {
                    const int r0 = wm*32 + m*16 + g;
                    const float b0 = bias[co0 + r0], b1 = bias[co0 + r0 + 8];
                    #pragma unroll
                    for (int nn = 0; nn < NT; nn++) {
                        const int pl = nn*8 + tig*2;
                        sE[pl*132 + r0]       = acc[m][nn][0] + b0;
                        sE[(pl+1)*132 + r0]   = acc[m][nn][1] + b0;
                        sE[pl*132 + r0+8]     = acc[m][nn][2] + b1;
                        sE[(pl+1)*132 + r0+8] = acc[m][nn][3] + b1;
                    }
                }
            }
            __syncthreads();
            #pragma unroll
            for (int i = 0; i < 8; i++) {
                int idx = tid + i*256;
                int pp = idx >> 5, c4 = idx & 31;
                float4 v = *(float4*)&sE[pp*132 + c4*4];
                *(float4*)(out0 + ((size_t)b*4096 + pix0 + pass*64 + pp)*256
                           + co0 + c4*4) = v;
            }
            if (STATS && tid < 128) {
                #pragma unroll 8
                for (int pp = 0; pp < 64; pp++) {
                    float v = sE[pp*132 + tid];
                    sc += v; sc2 += v*v;
                }
            }
            __syncthreads();
        }
        if (STATS && tid < 128) {
            ps[(co0 + tid)*256 + cta] = sc;
            pq[(co0 + tid)*256 + cta] = sc2;
        }
    } else {                                   // EPI 2: offsets + mask (M=32)
        #pragma unroll
        for (int m = 0; m < 2; m++)
            #pragma unroll
            for (int nn = 0; nn < NT; nn++) {
                const int r = m*16 + g;
                const int pl = wn*(NT*8) + nn*8 + tig*2;
                sE[r*132 + pl]       = acc[m][nn][0];
                sE[r*132 + pl+1]     = acc[m][nn][1];
                sE[(r+8)*132 + pl]   = acc[m][nn][2];
                sE[(r+8)*132 + pl+1] = acc[m][nn][3];
            }
        __syncthreads();
        if (tid < 128) {
            const int pix = pix0 + tid;
            #pragma unroll
            for (int r = 0; r < 27; r++) {
                float v = sE[r*132 + tid] + bias[r];
                if (r < 18) out0[((size_t)b*18 + r)*4096 + pix] = v;
                else        out1[((size_t)b*9 + r - 18)*4096 + pix] = 2.f/(1.f + expf(-v));
            }
        }
    }
}

// ---------------- stats combine: 256 partials -> mean/rstd ----------------------
__global__ __launch_bounds__(256) void bn_combine(const float* __restrict__ ps,
    const float* __restrict__ pq, float* __restrict__ st)
{
    const int c = threadIdx.x;
    float s = 0.f, s2 = 0.f;
    for (int j = 0; j < 256; j++) { s += ps[c*256 + j]; s2 += pq[c*256 + j]; }
    const float m = s * (1.f/32768.f);
    const float var = s2 * (1.f/32768.f) - m*m;
    st[c] = m;
    st[256 + c] = rsqrtf(var + 1e-5f);
}

// ---------------- prep kernels ----------------------------------------------------
__global__ __launch_bounds__(256) void permuteK_round(const float* __restrict__ in,
                                                      float* __restrict__ out)
{
    int i = blockIdx.x*256 + threadIdx.x;
    int co = i / KFULL, r = i - co*KFULL;
    int t = r >> 8, ci = r & 255;
    out[i] = f2tff(in[co*KFULL + ci*9 + t]);
}

__global__ __launch_bounds__(256) void pack_offmod_round(
    const float* __restrict__ w_off, const float* __restrict__ w_mod,
    const float* __restrict__ b_off, const float* __restrict__ b_mod,
    float* __restrict__ wp, float* __restrict__ bp)
{
    int i = blockIdx.x*256 + threadIdx.x;
    if (i < 32*KFULL) {
        int o = i / KFULL, r = i - o*KFULL;
        int t = r >> 8, ci = r & 255;
        float v = 0.f;
        if (o < 18)      v = w_off[o*KFULL + ci*9 + t];
        else if (o < 27) v = w_mod[(o-18)*KFULL + ci*9 + t];
        wp[i] = f2tff(v);
    }
    if (i < 27) bp[i] = (i < 18) ? b_off[i] : b_mod[i-18];
}

__global__ __launch_bounds__(256) void round_wds(const float* __restrict__ in,
                                                 float* __restrict__ out)
{
    int i = blockIdx.x*256 + threadIdx.x;
    out[i] = f2tff(in[i]);
}

// NCHW -> NHWC tf32-rounded (for x)
__global__ __launch_bounds__(256) void nhwc_round(const float* __restrict__ in,
                                                  float* __restrict__ out)
{
    __shared__ float tb[32][33];
    const int pix0 = blockIdx.x*32, c0 = blockIdx.y*32, b = blockIdx.z;
    const int tx = threadIdx.x & 31, ty = threadIdx.x >> 5;
    #pragma unroll
    for (int i = 0; i < 4; i++)
        tb[ty + i*8][tx] = f2tff(in[((size_t)b*256 + c0 + ty + i*8)*4096 + pix0 + tx]);
    __syncthreads();
    #pragma unroll
    for (int i = 0; i < 4; i++)
        out[((size_t)b*4096 + pix0 + ty + i*8)*256 + c0 + tx] = tb[tx][ty + i*8];
}

// in-place BN + ReLU + tf32 round on NHWC
__global__ __launch_bounds__(256) void bn_relu_nhwc(float* __restrict__ y,
    const float* __restrict__ st, const float* __restrict__ g, const float* __restrict__ bt)
{
    const int i = blockIdx.x*256 + threadIdx.x;
    const int c = i & 255;
    const float v = (y[i] - st[c]) * st[256 + c] * g[c] + bt[c];
    y[i] = f2tff(fmaxf(v, 0.f));
}

// ---------------- deformable gather on NHWC -> col [b][pix][k] -------------------
__global__ __launch_bounds__(288) void deform_sample(
    const float* __restrict__ y1h, const float* __restrict__ off,
    const float* __restrict__ msk, float* __restrict__ col)
{
    const int p = threadIdx.x >> 5, lane = threadIdx.x & 31;
    const int pix = blockIdx.x, b = blockIdx.y;
    const int ho = pix >> 6, wo = pix & 63;

    const float dy = off[((size_t)b*18 + 2*p    )*4096 + pix];
    const float dx = off[((size_t)b*18 + 2*p + 1)*4096 + pix];
    const float m  = msk[((size_t)b*9 + p)*4096 + pix];
    const float py = (float)(ho - 1 + p/3) + dy;
    const float px = (float)(wo - 1 + p%3) + dx;

    const float y0f = floorf(py), x0f = floorf(px);
    const float ly = py - y0f, lx = px - x0f;
    const int y0 = (int)y0f, x0 = (int)x0f;
    const int y1 = y0 + 1,  x1 = x0 + 1;
    float w00 = (1.f-ly)*(1.f-lx), w01 = (1.f-ly)*lx, w10 = ly*(1.f-lx), w11 = ly*lx;
    const bool vy0 = (y0 >= 0) && (y0 < 64), vy1 = (y1 >= 0) && (y1 < 64);
    const bool vx0 = (x0 >= 0) && (x0 < 64), vx1 = (x1 >= 0) && (x1 < 64);
    if (!(vy0 && vx0)) w00 = 0.f;
    if (!(vy0 && vx1)) w01 = 0.f;
    if (!(vy1 && vx0)) w10 = 0.f;
    if (!(vy1 && vx1)) w11 = 0.f;
    const int yc0 = min(max(y0, 0), 63), yc1 = min(max(y1, 0), 63);
    const int xc0 = min(max(x0, 0), 63), xc1 = min(max(x1, 0), 63);
    w00 *= m; w01 *= m; w10 *= m; w11 *= m;

    const float* base = y1h + (size_t)b*4096*256;
    const float* p00 = base + (size_t)(yc0*64 + xc0)*256 + lane*8;
    const float* p01 = base + (size_t)(yc0*64 + xc1)*256 + lane*8;
    const float* p10 = base + (size_t)(yc1*64 + xc0)*256 + lane*8;
    const float* p11 = base + (size_t)(yc1*64 + xc1)*256 + lane*8;
    float* cp = col + ((size_t)b*4096 + pix)*KFULL + p*256 + lane*8;

    #pragma unroll
    for (int h = 0; h < 2; h++) {
        const float4 a = *(const float4*)(p00 + h*4);
        const float4 c2 = *(const float4*)(p01 + h*4);
        const float4 d = *(const float4*)(p10 + h*4);
        const float4 e = *(const float4*)(p11 + h*4);
        float4 s;
        s.x = f2tff(w00*a.x + w01*c2.x + w10*d.x + w11*e.x);
        s.y = f2tff(w00*a.y + w01*c2.y + w10*d.y + w11*e.y);
        s.z = f2tff(w00*a.z + w01*c2.z + w10*d.z + w11*e.z);
        s.w = f2tff(w00*a.w + w01*c2.w + w10*d.w + w11*e.w);
        *(float4*)(cp + h*4) = s;
    }
}

// ---------------- final: relu( bn2(d2) + bn3(res) ) --------------------------------
__global__ __launch_bounds__(256) void final_fuse(
    const float* __restrict__ d2, const float* __restrict__ res,
    const float* __restrict__ st,
    const float* __restrict__ g2, const float* __restrict__ bt2,
    const float* __restrict__ g3, const float* __restrict__ bt3,
    float* __restrict__ out)
{
    const int i = blockIdx.x*256 + threadIdx.x;
    const int c = (i >> 12) & 255;
    const float a = (d2[i]  - st[512 + c])  * st[768 + c]  * g2[c] + bt2[c];
    const float r = (res[i] - st[1024 + c]) * st[1280 + c] * g3[c] + bt3[c];
    out[i] = fmaxf(a + r, 0.f);
}

// ---------------- launcher -----------------------------------------------------------
extern "C" void kernel_launch(void* const* d_in, const int* in_sizes, int n_in,
                              void* d_out, int out_size)
{
    const float* x     = (const float*)d_in[0];
    const float* w1    = (const float*)d_in[2];
    const float* b1    = (const float*)d_in[3];
    const float* g1    = (const float*)d_in[4];
    const float* bt1   = (const float*)d_in[5];
    const float* w_off = (const float*)d_in[6];
    const float* b_off = (const float*)d_in[7];
    const float* w_mod = (const float*)d_in[8];
    const float* b_mod = (const float*)d_in[9];
    const float* w_d   = (const float*)d_in[10];
    const float* b_d   = (const float*)d_in[11];
    const float* g2    = (const float*)d_in[12];
    const float* bt2   = (const float*)d_in[13];
    const float* w_ds  = (const float*)d_in[14];
    const float* b_ds  = (const float*)d_in[15];
    const float* g3    = (const float*)d_in[16];
    const float* bt3   = (const float*)d_in[17];

    float *xt, *y1h, *d2, *res, *off, *msk, *col, *st, *ps, *pq;
    float *w1p, *wdp, *wop, *wds, *bp;
    cudaGetSymbolAddress((void**)&xt,  g_xt);
    cudaGetSymbolAddress((void**)&y1h, g_y1h);
    cudaGetSymbolAddress((void**)&d2,  g_d2);
    cudaGetSymbolAddress((void**)&res, g_res);
    cudaGetSymbolAddress((void**)&off, g_off);
    cudaGetSymbolAddress((void**)&msk, g_mask);
    cudaGetSymbolAddress((void**)&col, g_col);
    cudaGetSymbolAddress((void**)&st,  g_stats);
    cudaGetSymbolAddress((void**)&ps,  g_ps);
    cudaGetSymbolAddress((void**)&pq,  g_pq);
    cudaGetSymbolAddress((void**)&w1p, g_w1p);
    cudaGetSymbolAddress((void**)&wdp, g_wdp);
    cudaGetSymbolAddress((void**)&wop, g_wop);
    cudaGetSymbolAddress((void**)&wds, g_wds);
    cudaGetSymbolAddress((void**)&bp,  g_bp);

    const int SM128 = 2 * (128*36 + 128*36) * 4;   // 73728
    const int SM32  = 2 * (32*36  + 128*36) * 4;   // 46080
    cudaFuncSetAttribute(gemm_v4<128,1,1,true>,  cudaFuncAttributeMaxDynamicSharedMemorySize, SM128);
    cudaFuncSetAttribute(gemm_v4<128,0,0,true>,  cudaFuncAttributeMaxDynamicSharedMemorySize, SM128);
    cudaFuncSetAttribute(gemm_v4<32,1,2,false>,  cudaFuncAttributeMaxDynamicSharedMemorySize, SM32);

    // 0) prep
    nhwc_round<<<dim3(128, 8, BN), 256>>>(x, xt);
    permuteK_round<<<256*KFULL/256, 256>>>(w1,  w1p);
    permuteK_round<<<256*KFULL/256, 256>>>(w_d, wdp);
    pack_offmod_round<<<32*KFULL/256, 256>>>(w_off, w_mod, b_off, b_mod, wop, bp);
    round_wds<<<256*256/256, 256>>>(w_ds, wds);

    // 1) conv1: implicit 3x3 GEMM -> y1h NHWC raw + fused stats partials
    gemm_v4<128,1,1,true><<<dim3(32, 2, BN), 256, SM128>>>(
        w1p, xt, b1, y1h, nullptr, ps, pq, KFULL, 0);
    bn_combine<<<1, 256>>>(ps, pq, st);
    // 2) BN1 + ReLU + round, in place
    bn_relu_nhwc<<<(int)((size_t)BN*HWn*C/256), 256>>>(y1h, st, g1, bt1);
    // 3) offsets + modulation
    gemm_v4<32,1,2,false><<<dim3(32, 1, BN), 256, SM32>>>(
        wop, y1h, bp, off, msk, nullptr, nullptr, KFULL, 0);
    // 4) bilinear gather -> col [b][pix][k] (separate streaming kernel — R6 form)
    deform_sample<<<dim3(HWn, BN), 288>>>(y1h, off, msk, col);
    // 5) deformable GEMM (K=2304) -> d2 NCHW + fused stats
    gemm_v4<128,0,0,true><<<dim3(32, 2, BN), 256, SM128>>>(
        wdp, col, b_d, d2, nullptr, ps + 65536, pq + 65536, KFULL, KFULL);
    // 6) 1x1 shortcut -> res NCHW + fused stats
    gemm_v4<128,0,0,true><<<dim3(32, 2, BN), 256, SM128>>>(
        wds, xt, b_ds, res, nullptr, ps + 2*65536, pq + 2*65536, 256, 256);
    bn_combine<<<1, 256>>>(ps + 65536,   pq + 65536,   st + 512);
    bn_combine<<<1, 256>>>(ps + 2*65536, pq + 2*65536, st + 1024);
    // 7) fused BN2 + BN3 + add + ReLU
    final_fuse<<<BN*C*HWn/256, 256>>>(d2, res, st, g2, bt2, g3, bt3, (float*)d_out);
}

// round 9
// speedup vs baseline: 1.2306x; 1.1901x over previous
#include <cuda_runtime.h>
#include <math.h>
#include <stdint.h>

#define BN 8
#define C 256
#define HWn 4096
#define KFULL 2304

// ---------------- scratch (device globals: allocation-free) ----------------
__device__ float g_xt [(size_t)BN*HWn*C];        // x NHWC, tf32-rounded
__device__ float g_y1h[(size_t)BN*HWn*C];        // conv1 NHWC raw -> (in place) bn+relu rounded
__device__ float g_d2 [(size_t)BN*C*HWn];        // deform conv raw NCHW
__device__ float g_res[(size_t)BN*C*HWn];        // 1x1 raw NCHW
__device__ float g_off[BN*18*HWn];
__device__ float g_mask[BN*9*HWn];
__device__ float g_col[(size_t)BN*HWn*KFULL];    // [b][pix][k=p*256+ci], rounded
__device__ float g_stats[6*256];
__device__ float g_ps[3*256*256];                // [cta][c]  (coalesced combine)
__device__ float g_pq[3*256*256];
__device__ float g_w1p[256*KFULL];               // w1  -> [co][t*256+ci] rounded
__device__ float g_wdp[256*KFULL];               // w_d -> [co][t*256+ci] rounded
__device__ float g_wop[32*KFULL];                // off+mod packed (27 rows + 5 zero)
__device__ float g_wds[256*256];                 // w_ds rounded
__device__ float g_bp[32];

// ---------------- helpers -----------------------------------------------------
__device__ __forceinline__ unsigned f2tf(float v) {
    unsigned u; asm("cvt.rna.tf32.f32 %0, %1;" : "=r"(u) : "f"(v)); return u;
}
__device__ __forceinline__ float f2tff(float v) { return __uint_as_float(f2tf(v)); }
__device__ __forceinline__ uint32_t s2u(const void* p) {
    uint32_t a;
    asm("{ .reg .u64 t; cvta.to.shared.u64 t, %1; cvt.u32.u64 %0, t; }" : "=r"(a) : "l"(p));
    return a;
}
__device__ __forceinline__ void cpa16(uint32_t dst, const void* src, bool v) {
    int sz = v ? 16 : 0;
    asm volatile("cp.async.cg.shared.global [%0], [%1], 16, %2;"
                 :: "r"(dst), "l"(src), "r"(sz) : "memory");
}
__device__ __forceinline__ void mma8(float* d, const uint4& a, const uint2& b) {
    asm volatile("mma.sync.aligned.m16n8k8.row.col.f32.tf32.tf32.f32 "
        "{%0,%1,%2,%3}, {%4,%5,%6,%7}, {%8,%9}, {%0,%1,%2,%3};"
        : "+f"(d[0]), "+f"(d[1]), "+f"(d[2]), "+f"(d[3])
        : "r"(a.x), "r"(a.y), "r"(a.z), "r"(a.w), "r"(b.x), "r"(b.y));
}

// ---------------- unified tf32 GEMM, cp.async double-buffered -------------------
// D[M co x 128 pix] = A[co][k] * B[k][pix], K chunks of 32, 256 threads.
// BMODE 0: B[k][pix] = Bm[(b*4096+pix)*ROWLEN + k]
// BMODE 1: implicit 3x3 im2col of NHWC Bm, k = t*256+ci (zero-fill via cp.async)
// EPI 0: NCHW out (+bias).  EPI 1: NHWC out (+bias).  EPI 2: offsets/mask.
// STATS: per-channel partial sum/sumsq -> ps/pq[cta*256 + c].
template<int M, int BMODE, int EPI, bool STATS>
__global__ void __launch_bounds__(256, 2) gemm_v4(
    const float* __restrict__ A, const float* __restrict__ Bm,
    const float* __restrict__ bias,
    float* __restrict__ out0, float* __restrict__ out1,
    float* __restrict__ ps, float* __restrict__ pq,
    int Kdim, int ROWLEN)
{
    constexpr int WN = 256 / M;
    constexpr int NT = M / 16;
    constexpr int APITCH = 36;
    constexpr int ABUF = M * APITCH;
    constexpr int BBUF = 128 * APITCH;
    constexpr int STAGE = ABUF + BBUF;

    extern __shared__ float sm[];
    const int tid = threadIdx.x, lane = tid & 31, warp = tid >> 5;
    const int wm = warp / WN, wn = warp % WN;
    const int g = lane >> 2, tig = lane & 3;
    const int pix0 = blockIdx.x * 128, co0 = blockIdx.y * M, b = blockIdx.z;
    const int cta = blockIdx.x + (blockIdx.z << 5);
    const uint32_t smu = s2u(sm);

    float acc[2][NT][4] = {};
    const int nch = Kdim >> 5;

    auto stage = [&](int ic, int buf) {
        const int k0 = ic << 5;
        uint32_t sA = smu + buf * STAGE * 4;
        uint32_t sB = sA + ABUF * 4;
        #pragma unroll
        for (int i = 0; i < M/32; i++) {            // A: M x 32k
            int idx = tid + i*256;
            int row = idx >> 3, kq = idx & 7;
            cpa16(sA + (row*APITCH + kq*4)*4,
                  A + (size_t)(co0+row)*Kdim + k0 + kq*4, true);
        }
        int ty = 0, tx = 0, ci0 = 0;
        if (BMODE == 1) { int t = k0 >> 8; ty = t/3 - 1; tx = t%3 - 1; ci0 = k0 & 255; }
        #pragma unroll
        for (int i = 0; i < 4; i++) {               // B: 32k x 128pix
            int idx = tid + i*256;
            int pp = idx >> 3, kq = idx & 7;
            uint32_t dst = sB + (pp*APITCH + kq*4)*4;
            if (BMODE == 1) {
                int pix = pix0 + pp;
                int py = (pix >> 6) + ty, px = (pix & 63) + tx;
                bool v = (py >= 0) && (py < 64) && (px >= 0) && (px < 64);
                cpa16(dst, Bm + ((size_t)b*4096 + (v ? (py*64+px) : 0))*256
                           + ci0 + kq*4, v);
            } else {
                cpa16(dst, Bm + ((size_t)b*4096 + pix0 + pp)*(size_t)ROWLEN
                           + k0 + kq*4, true);
            }
        }
        asm volatile("cp.async.commit_group;" ::: "memory");
    };

    stage(0, 0);
    for (int ic = 0; ic < nch; ic++) {
        const int buf = ic & 1;
        if (ic + 1 < nch) {
            stage(ic + 1, buf ^ 1);
            asm volatile("cp.async.wait_group 1;" ::: "memory");
        } else {
            asm volatile("cp.async.wait_group 0;" ::: "memory");
        }
        __syncthreads();
        const float* sA = sm + buf*STAGE;
        const float* sB = sA + ABUF;
        #pragma unroll
        for (int k8 = 0; k8 < 4; k8++) {
            const int kb = k8 * 8;
            uint4 af[2];
            #pragma unroll
            for (int m = 0; m < 2; m++) {
                const int cw = wm*32 + m*16;
                af[m].x = __float_as_uint(sA[(cw+g  )*APITCH + kb+tig  ]);
                af[m].y = __float_as_uint(sA[(cw+g+8)*APITCH + kb+tig  ]);
                af[m].z = __float_as_uint(sA[(cw+g  )*APITCH + kb+tig+4]);
                af[m].w = __float_as_uint(sA[(cw+g+8)*APITCH + kb+tig+4]);
            }
            #pragma unroll
            for (int nn = 0; nn < NT; nn++) {
                const int pc = wn*(NT*8) + nn*8 + g;
                uint2 bb;
                bb.x = __float_as_uint(sB[pc*APITCH + kb+tig  ]);
                bb.y = __float_as_uint(sB[pc*APITCH + kb+tig+4]);
                mma8(acc[0][nn], af[0], bb);
                mma8(acc[1][nn], af[1], bb);
            }
        }
        __syncthreads();
    }

    // ---- epilogue (reuses smem) ----
    float* sE = sm;
    if (EPI == 0) {                            // NCHW out, bias at fill, opt stats
        #pragma unroll
        for (int p = 0; p < M/32; p++) {
            if (wm == p) {
                #pragma unroll
                for (int m = 0; m < 2; m++) {
                    const int r = m*16 + g;
                    const float b0 = bias[co0 + p*32 + r];
                    const float b1 = bias[co0 + p*32 + r + 8];
                    #pragma unroll
                    for (int nn = 0; nn < NT; nn++) {
                        const int pl = wn*(NT*8) + nn*8 + tig*2;
                        sE[r*132 + pl]       = acc[m][nn][0] + b0;
                        sE[r*132 + pl+1]     = acc[m][nn][1] + b0;
                        sE[(r+8)*132 + pl]   = acc[m][nn][2] + b1;
                        sE[(r+8)*132 + pl+1] = acc[m][nn][3] + b1;
                    }
                }
            }
            __syncthreads();
            #pragma unroll
            for (int i = 0; i < 4; i++) {
                int idx = tid + i*256;
                int r = idx >> 5, p4 = idx & 31;
                float4 v = *(float4*)&sE[r*132 + p4*4];
                *(float4*)(out0 + (((size_t)b*256 + co0 + p*32 + r) << 12)
                           + pix0 + p4*4) = v;
                if (STATS) {
                    float s  = v.x + v.y + v.z + v.w;
                    float s2 = v.x*v.x + v.y*v.y + v.z*v.z + v.w*v.w;
                    #pragma unroll
                    for (int o = 16; o > 0; o >>= 1) {
                        s  += __shfl_xor_sync(0xffffffffu, s,  o);
                        s2 += __shfl_xor_sync(0xffffffffu, s2, o);
                    }
                    if (lane == 0) {
                        ps[cta*256 + co0 + p*32 + r] = s;
                        pq[cta*256 + co0 + p*32 + r] = s2;
                    }
                }
            }
            __syncthreads();
        }
    } else if (EPI == 1) {                     // NHWC out (M=128, WN=2), opt stats
        float sc = 0.f, sc2 = 0.f;
        #pragma unroll
        for (int pass = 0; pass < 2; pass++) {
            if (wn == pass) {
                #pragma unroll
                for (int m = 0; m < 2; m++) {
                    const int r0 = wm*32 + m*16 + g;
                    const float b0 = bias[co0 + r0], b1 = bias[co0 + r0 + 8];
                    #pragma unroll
                    for (int nn = 0; nn < NT; nn++) {
                        const int pl = nn*8 + tig*2;
                        sE[pl*132 + r0]       = acc[m][nn][0] + b0;
                        sE[(pl+1)*132 + r0]   = acc[m][nn][1] + b0;
                        sE[pl*132 + r0+8]     = acc[m][nn][2] + b1;
                        sE[(pl+1)*132 + r0+8] = acc[m][nn][3] + b1;
                    }
                }
            }
            __syncthreads();
            #pragma unroll
            for (int i = 0; i < 8; i++) {
                int idx = tid + i*256;
                int pp = idx >> 5, c4 = idx & 31;
                float4 v = *(float4*)&sE[pp*132 + c4*4];
                *(float4*)(out0 + ((size_t)b*4096 + pix0 + pass*64 + pp)*256
                           + co0 + c4*4) = v;
            }
            if (STATS && tid < 128) {
                #pragma unroll 8
                for (int pp = 0; pp < 64; pp++) {
                    float v = sE[pp*132 + tid];
                    sc += v; sc2 += v*v;
                }
            }
            __syncthreads();
        }
        if (STATS && tid < 128) {
            ps[cta*256 + co0 + tid] = sc;
            pq[cta*256 + co0 + tid] = sc2;
        }
    } else {                                   // EPI 2: offsets + mask (M=32)
        #pragma unroll
        for (int m = 0; m < 2; m++)
            #pragma unroll
            for (int nn = 0; nn < NT; nn++) {
                const int r = m*16 + g;
                const int pl = wn*(NT*8) + nn*8 + tig*2;
                sE[r*132 + pl]       = acc[m][nn][0];
                sE[r*132 + pl+1]     = acc[m][nn][1];
                sE[(r+8)*132 + pl]   = acc[m][nn][2];
                sE[(r+8)*132 + pl+1] = acc[m][nn][3];
            }
        __syncthreads();
        if (tid < 128) {
            const int pix = pix0 + tid;
            #pragma unroll
            for (int r = 0; r < 27; r++) {
                float v = sE[r*132 + tid] + bias[r];
                if (r < 18) out0[((size_t)b*18 + r)*4096 + pix] = v;
                else        out1[((size_t)b*9 + r - 18)*4096 + pix] = 2.f/(1.f + expf(-v));
            }
        }
    }
}

// ---------------- stats combine: 256 partials -> mean/rstd (coalesced) ----------
__global__ __launch_bounds__(256) void bn_combine(const float* __restrict__ ps,
    const float* __restrict__ pq, float* __restrict__ st)
{
    const int c = threadIdx.x;
    float s = 0.f, s2 = 0.f;
    #pragma unroll 8
    for (int j = 0; j < 256; j++) { s += ps[j*256 + c]; s2 += pq[j*256 + c]; }
    const float m = s * (1.f/32768.f);
    const float var = s2 * (1.f/32768.f) - m*m;
    st[c] = m;
    st[256 + c] = rsqrtf(var + 1e-5f);
}

// ---------------- prep kernels ----------------------------------------------------
__global__ __launch_bounds__(256) void permuteK_round(const float* __restrict__ in,
                                                      float* __restrict__ out)
{
    int i = blockIdx.x*256 + threadIdx.x;
    int co = i / KFULL, r = i - co*KFULL;
    int t = r >> 8, ci = r & 255;
    out[i] = f2tff(in[co*KFULL + ci*9 + t]);
}

__global__ __launch_bounds__(256) void pack_offmod_round(
    const float* __restrict__ w_off, const float* __restrict__ w_mod,
    const float* __restrict__ b_off, const float* __restrict__ b_mod,
    float* __restrict__ wp, float* __restrict__ bp)
{
    int i = blockIdx.x*256 + threadIdx.x;
    if (i < 32*KFULL) {
        int o = i / KFULL, r = i - o*KFULL;
        int t = r >> 8, ci = r & 255;
        float v = 0.f;
        if (o < 18)      v = w_off[o*KFULL + ci*9 + t];
        else if (o < 27) v = w_mod[(o-18)*KFULL + ci*9 + t];
        wp[i] = f2tff(v);
    }
    if (i < 27) bp[i] = (i < 18) ? b_off[i] : b_mod[i-18];
}

__global__ __launch_bounds__(256) void round_wds(const float* __restrict__ in,
                                                 float* __restrict__ out)
{
    int i = blockIdx.x*256 + threadIdx.x;
    out[i] = f2tff(in[i]);
}

// NCHW -> NHWC tf32-rounded (for x)
__global__ __launch_bounds__(256) void nhwc_round(const float* __restrict__ in,
                                                  float* __restrict__ out)
{
    __shared__ float tb[32][33];
    const int pix0 = blockIdx.x*32, c0 = blockIdx.y*32, b = blockIdx.z;
    const int tx = threadIdx.x & 31, ty = threadIdx.x >> 5;
    #pragma unroll
    for (int i = 0; i < 4; i++)
        tb[ty + i*8][tx] = f2tff(in[((size_t)b*256 + c0 + ty + i*8)*4096 + pix0 + tx]);
    __syncthreads();
    #pragma unroll
    for (int i = 0; i < 4; i++)
        out[((size_t)b*4096 + pix0 + ty + i*8)*256 + c0 + tx] = tb[tx][ty + i*8];
}

// in-place BN + ReLU + tf32 round on NHWC
__global__ __launch_bounds__(256) void bn_relu_nhwc(float* __restrict__ y,
    const float* __restrict__ st, const float* __restrict__ g, const float* __restrict__ bt)
{
    const int i = blockIdx.x*256 + threadIdx.x;
    const int c = i & 255;
    const float v = (y[i] - st[c]) * st[256 + c] * g[c] + bt[c];
    y[i] = f2tff(fmaxf(v, 0.f));
}

// ---------------- deformable gather on NHWC -> col [b][pix][k] -------------------
__global__ __launch_bounds__(288) void deform_sample(
    const float* __restrict__ y1h, const float* __restrict__ off,
    const float* __restrict__ msk, float* __restrict__ col)
{
    const int p = threadIdx.x >> 5, lane = threadIdx.x & 31;
    const int pix = blockIdx.x, b = blockIdx.y;
    const int ho = pix >> 6, wo = pix & 63;

    const float dy = off[((size_t)b*18 + 2*p    )*4096 + pix];
    const float dx = off[((size_t)b*18 + 2*p + 1)*4096 + pix];
    const float m  = msk[((size_t)b*9 + p)*4096 + pix];
    const float py = (float)(ho - 1 + p/3) + dy;
    const float px = (float)(wo - 1 + p%3) + dx;

    const float y0f = floorf(py), x0f = floorf(px);
    const float ly = py - y0f, lx = px - x0f;
    const int y0 = (int)y0f, x0 = (int)x0f;
    const int y1 = y0 + 1,  x1 = x0 + 1;
    float w00 = (1.f-ly)*(1.f-lx), w01 = (1.f-ly)*lx, w10 = ly*(1.f-lx), w11 = ly*lx;
    const bool vy0 = (y0 >= 0) && (y0 < 64), vy1 = (y1 >= 0) && (y1 < 64);
    const bool vx0 = (x0 >= 0) && (x0 < 64), vx1 = (x1 >= 0) && (x1 < 64);
    if (!(vy0 && vx0)) w00 = 0.f;
    if (!(vy0 && vx1)) w01 = 0.f;
    if (!(vy1 && vx0)) w10 = 0.f;
    if (!(vy1 && vx1)) w11 = 0.f;
    const int yc0 = min(max(y0, 0), 63), yc1 = min(max(y1, 0), 63);
    const int xc0 = min(max(x0, 0), 63), xc1 = min(max(x1, 0), 63);
    w00 *= m; w01 *= m; w10 *= m; w11 *= m;

    const float* base = y1h + (size_t)b*4096*256;
    const float* p00 = base + (size_t)(yc0*64 + xc0)*256 + lane*8;
    const float* p01 = base + (size_t)(yc0*64 + xc1)*256 + lane*8;
    const float* p10 = base + (size_t)(yc1*64 + xc0)*256 + lane*8;
    const float* p11 = base + (size_t)(yc1*64 + xc1)*256 + lane*8;
    float* cp = col + ((size_t)b*4096 + pix)*KFULL + p*256 + lane*8;

    #pragma unroll
    for (int h = 0; h < 2; h++) {
        const float4 a = *(const float4*)(p00 + h*4);
        const float4 c2 = *(const float4*)(p01 + h*4);
        const float4 d = *(const float4*)(p10 + h*4);
        const float4 e = *(const float4*)(p11 + h*4);
        float4 s;
        s.x = f2tff(w00*a.x + w01*c2.x + w10*d.x + w11*e.x);
        s.y = f2tff(w00*a.y + w01*c2.y + w10*d.y + w11*e.y);
        s.z = f2tff(w00*a.z + w01*c2.z + w10*d.z + w11*e.z);
        s.w = f2tff(w00*a.w + w01*c2.w + w10*d.w + w11*e.w);
        *(float4*)(cp + h*4) = s;
    }
}

// ---------------- final: relu( bn2(d2) + bn3(res) ) --------------------------------
__global__ __launch_bounds__(256) void final_fuse(
    const float* __restrict__ d2, const float* __restrict__ res,
    const float* __restrict__ st,
    const float* __restrict__ g2, const float* __restrict__ bt2,
    const float* __restrict__ g3, const float* __restrict__ bt3,
    float* __restrict__ out)
{
    const int i = blockIdx.x*256 + threadIdx.x;
    const int c = (i >> 12) & 255;
    const float a = (d2[i]  - st[512 + c])  * st[768 + c]  * g2[c] + bt2[c];
    const float r = (res[i] - st[1024 + c]) * st[1280 + c] * g3[c] + bt3[c];
    out[i] = fmaxf(a + r, 0.f);
}

// ---------------- launcher -----------------------------------------------------------
extern "C" void kernel_launch(void* const* d_in, const int* in_sizes, int n_in,
                              void* d_out, int out_size)
{
    const float* x     = (const float*)d_in[0];
    const float* w1    = (const float*)d_in[2];
    const float* b1    = (const float*)d_in[3];
    const float* g1    = (const float*)d_in[4];
    const float* bt1   = (const float*)d_in[5];
    const float* w_off = (const float*)d_in[6];
    const float* b_off = (const float*)d_in[7];
    const float* w_mod = (const float*)d_in[8];
    const float* b_mod = (const float*)d_in[9];
    const float* w_d   = (const float*)d_in[10];
    const float* b_d   = (const float*)d_in[11];
    const float* g2    = (const float*)d_in[12];
    const float* bt2   = (const float*)d_in[13];
    const float* w_ds  = (const float*)d_in[14];
    const float* b_ds  = (const float*)d_in[15];
    const float* g3    = (const float*)d_in[16];
    const float* bt3   = (const float*)d_in[17];

    float *xt, *y1h, *d2, *res, *off, *msk, *col, *st, *ps, *pq;
    float *w1p, *wdp, *wop, *wds, *bp;
    cudaGetSymbolAddress((void**)&xt,  g_xt);
    cudaGetSymbolAddress((void**)&y1h, g_y1h);
    cudaGetSymbolAddress((void**)&d2,  g_d2);
    cudaGetSymbolAddress((void**)&res, g_res);
    cudaGetSymbolAddress((void**)&off, g_off);
    cudaGetSymbolAddress((void**)&msk, g_mask);
    cudaGetSymbolAddress((void**)&col, g_col);
    cudaGetSymbolAddress((void**)&st,  g_stats);
    cudaGetSymbolAddress((void**)&ps,  g_ps);
    cudaGetSymbolAddress((void**)&pq,  g_pq);
    cudaGetSymbolAddress((void**)&w1p, g_w1p);
    cudaGetSymbolAddress((void**)&wdp, g_wdp);
    cudaGetSymbolAddress((void**)&wop, g_wop);
    cudaGetSymbolAddress((void**)&wds, g_wds);
    cudaGetSymbolAddress((void**)&bp,  g_bp);

    const int SM128 = 2 * (128*36 + 128*36) * 4;   // 73728
    const int SM32  = 2 * (32*36  + 128*36) * 4;   // 46080
    cudaFuncSetAttribute(gemm_v4<128,1,1,true>,  cudaFuncAttributeMaxDynamicSharedMemorySize, SM128);
    cudaFuncSetAttribute(gemm_v4<128,0,0,true>,  cudaFuncAttributeMaxDynamicSharedMemorySize, SM128);
    cudaFuncSetAttribute(gemm_v4<32,1,2,false>,  cudaFuncAttributeMaxDynamicSharedMemorySize, SM32);

    // 0) prep
    nhwc_round<<<dim3(128, 8, BN), 256>>>(x, xt);
    permuteK_round<<<256*KFULL/256, 256>>>(w1,  w1p);
    permuteK_round<<<256*KFULL/256, 256>>>(w_d, wdp);
    pack_offmod_round<<<32*KFULL/256, 256>>>(w_off, w_mod, b_off, b_mod, wop, bp);
    round_wds<<<256*256/256, 256>>>(w_ds, wds);

    // 1) conv1: implicit 3x3 GEMM -> y1h NHWC raw + fused stats partials
    gemm_v4<128,1,1,true><<<dim3(32, 2, BN), 256, SM128>>>(
        w1p, xt, b1, y1h, nullptr, ps, pq, KFULL, 0);
    bn_combine<<<1, 256>>>(ps, pq, st);
    // 2) BN1 + ReLU + round, in place
    bn_relu_nhwc<<<(int)((size_t)BN*HWn*C/256), 256>>>(y1h, st, g1, bt1);
    // 3) offsets + modulation
    gemm_v4<32,1,2,false><<<dim3(32, 1, BN), 256, SM32>>>(
        wop, y1h, bp, off, msk, nullptr, nullptr, KFULL, 0);
    // 4) bilinear gather -> col [b][pix][k]
    deform_sample<<<dim3(HWn, BN), 288>>>(y1h, off, msk, col);
    // 5) deformable GEMM (K=2304) -> d2 NCHW + fused stats
    gemm_v4<128,0,0,true><<<dim3(32, 2, BN), 256, SM128>>>(
        wdp, col, b_d, d2, nullptr, ps + 65536, pq + 65536, KFULL, KFULL);
    // 6) 1x1 shortcut -> res NCHW + fused stats
    gemm_v4<128,0,0,true><<<dim3(32, 2, BN), 256, SM128>>>(
        wds, xt, b_ds, res, nullptr, ps + 2*65536, pq + 2*65536, 256, 256);
    bn_combine<<<1, 256>>>(ps + 65536,   pq + 65536,   st + 512);
    bn_combine<<<1, 256>>>(ps + 2*65536, pq + 2*65536, st + 1024);
    // 7) fused BN2 + BN3 + add + ReLU
    final_fuse<<<BN*C*HWn/256, 256>>>(d2, res, st, g2, bt2, g3, bt3, (float*)d_out);
}

// round 10
// speedup vs baseline: 1.2452x; 1.0118x over previous
#include <cuda_runtime.h>
#include <math.h>
#include <stdint.h>

#define BN 8
#define C 256
#define HWn 4096
#define KFULL 2304

// ---------------- scratch (device globals: allocation-free) ----------------
__device__ float g_xt [(size_t)BN*HWn*C];        // x NHWC, tf32-rounded
__device__ float g_y1h[(size_t)BN*HWn*C];        // conv1 NHWC raw -> (in place) bn+relu rounded
__device__ float g_d2 [(size_t)BN*C*HWn];        // deform conv raw NCHW
__device__ float g_res[(size_t)BN*C*HWn];        // 1x1 raw NCHW
__device__ float g_off[BN*18*HWn];
__device__ float g_mask[BN*9*HWn];
__device__ float g_col[(size_t)BN*HWn*KFULL];    // [b][pix][k=p*256+ci], rounded
__device__ float g_stats[6*256];
__device__ float g_ps[3*256*256];                // [cta][c]
__device__ float g_pq[3*256*256];
__device__ float g_w1p[256*KFULL];
__device__ float g_wdp[256*KFULL];
__device__ float g_wop[32*KFULL];
__device__ float g_wds[256*256];
__device__ float g_bp[32];

// ---------------- helpers -----------------------------------------------------
__device__ __forceinline__ unsigned f2tf(float v) {
    unsigned u; asm("cvt.rna.tf32.f32 %0, %1;" : "=r"(u) : "f"(v)); return u;
}
__device__ __forceinline__ float f2tff(float v) { return __uint_as_float(f2tf(v)); }
__device__ __forceinline__ uint32_t s2u(const void* p) {
    uint32_t a;
    asm("{ .reg .u64 t; cvta.to.shared.u64 t, %1; cvt.u32.u64 %0, t; }" : "=r"(a) : "l"(p));
    return a;
}
__device__ __forceinline__ void cpa16(uint32_t dst, const void* src, bool v) {
    int sz = v ? 16 : 0;
    asm volatile("cp.async.cg.shared.global [%0], [%1], 16, %2;"
                 :: "r"(dst), "l"(src), "r"(sz) : "memory");
}
__device__ __forceinline__ void mma8(float* d, const uint4& a, const uint2& b) {
    asm volatile("mma.sync.aligned.m16n8k8.row.col.f32.tf32.tf32.f32 "
        "{%0,%1,%2,%3}, {%4,%5,%6,%7}, {%8,%9}, {%0,%1,%2,%3};"
        : "+f"(d[0]), "+f"(d[1]), "+f"(d[2]), "+f"(d[3])
        : "r"(a.x), "r"(a.y), "r"(a.z), "r"(a.w), "r"(b.x), "r"(b.y));
}

// ---------------- GEMM core: 3-stage cp.async, tf32 mma -------------------------
// D[M co x 128 pix] = A[co][k] * B[k][pix]; K chunks of 32; 256 threads.
// BMODE 0: B[k][pix] = Bm[(b*4096+pix)*ROWLEN + k]
// BMODE 1: implicit 3x3 im2col of NHWC Bm, k = t*256+ci (zero-fill)
// EPI 0: NCHW out (+bias).  EPI 1: NHWC out (+bias).  EPI 2: offsets/mask.
// STATS: per-channel partials -> ps/pq[cta*256 + c].
template<int M, int BMODE, int EPI, bool STATS>
__device__ __forceinline__ void gemm_core(
    const float* __restrict__ A, const float* __restrict__ Bm,
    const float* __restrict__ bias,
    float* __restrict__ out0, float* __restrict__ out1,
    float* __restrict__ ps, float* __restrict__ pq,
    int Kdim, int ROWLEN, int pix0, int co0, int b, int cta, float* sm)
{
    constexpr int WN = 256 / M;
    constexpr int NT = M / 16;
    constexpr int APITCH = 36;
    constexpr int ABUF = M * APITCH;
    constexpr int BBUF = 128 * APITCH;
    constexpr int STAGE = ABUF + BBUF;

    const int tid = threadIdx.x, lane = tid & 31, warp = tid >> 5;
    const int wm = warp / WN, wn = warp % WN;
    const int g = lane >> 2, tig = lane & 3;
    const uint32_t smu = s2u(sm);

    float acc[2][NT][4] = {};
    const int nch = Kdim >> 5;

    auto stage = [&](int ic, int buf) {
        const int k0 = ic << 5;
        uint32_t sA = smu + buf * STAGE * 4;
        uint32_t sB = sA + ABUF * 4;
        #pragma unroll
        for (int i = 0; i < M/32; i++) {            // A: M x 32k
            int idx = tid + i*256;
            int row = idx >> 3, kq = idx & 7;
            cpa16(sA + (row*APITCH + kq*4)*4,
                  A + (size_t)(co0+row)*Kdim + k0 + kq*4, true);
        }
        int ty = 0, tx = 0, ci0 = 0;
        if (BMODE == 1) { int t = k0 >> 8; ty = t/3 - 1; tx = t%3 - 1; ci0 = k0 & 255; }
        #pragma unroll
        for (int i = 0; i < 4; i++) {               // B: 32k x 128pix
            int idx = tid + i*256;
            int pp = idx >> 3, kq = idx & 7;
            uint32_t dst = sB + (pp*APITCH + kq*4)*4;
            if (BMODE == 1) {
                int pix = pix0 + pp;
                int py = (pix >> 6) + ty, px = (pix & 63) + tx;
                bool v = (py >= 0) && (py < 64) && (px >= 0) && (px < 64);
                cpa16(dst, Bm + ((size_t)b*4096 + (v ? (py*64+px) : 0))*256
                           + ci0 + kq*4, v);
            } else {
                cpa16(dst, Bm + ((size_t)b*4096 + pix0 + pp)*(size_t)ROWLEN
                           + k0 + kq*4, true);
            }
        }
        asm volatile("cp.async.commit_group;" ::: "memory");
    };

    stage(0, 0);
    stage(1, 1);
    for (int ic = 0; ic < nch; ic++) {
        const int buf = ic % 3;
        if (ic + 2 < nch) {
            stage(ic + 2, (ic + 2) % 3);
            asm volatile("cp.async.wait_group 2;" ::: "memory");
        } else if (ic + 1 < nch) {
            asm volatile("cp.async.wait_group 1;" ::: "memory");
        } else {
            asm volatile("cp.async.wait_group 0;" ::: "memory");
        }
        __syncthreads();
        const float* sA = sm + buf*STAGE;
        const float* sB = sA + ABUF;
        #pragma unroll
        for (int k8 = 0; k8 < 4; k8++) {
            const int kb = k8 * 8;
            uint4 af[2];
            #pragma unroll
            for (int m = 0; m < 2; m++) {
                const int cw = wm*32 + m*16;
                af[m].x = __float_as_uint(sA[(cw+g  )*APITCH + kb+tig  ]);
                af[m].y = __float_as_uint(sA[(cw+g+8)*APITCH + kb+tig  ]);
                af[m].z = __float_as_uint(sA[(cw+g  )*APITCH + kb+tig+4]);
                af[m].w = __float_as_uint(sA[(cw+g+8)*APITCH + kb+tig+4]);
            }
            #pragma unroll
            for (int nn = 0; nn < NT; nn++) {
                const int pc = wn*(NT*8) + nn*8 + g;
                uint2 bb;
                bb.x = __float_as_uint(sB[pc*APITCH + kb+tig  ]);
                bb.y = __float_as_uint(sB[pc*APITCH + kb+tig+4]);
                mma8(acc[0][nn], af[0], bb);
                mma8(acc[1][nn], af[1], bb);
            }
        }
        __syncthreads();
    }

    // ---- epilogue (reuses smem) ----
    float* sE = sm;
    if (EPI == 0) {
        #pragma unroll
        for (int p = 0; p < M/32; p++) {
            if (wm == p) {
                #pragma unroll
                for (int m = 0; m < 2; m++) {
                    const int r = m*16 + g;
                    const float b0 = bias[co0 + p*32 + r];
                    const float b1 = bias[co0 + p*32 + r + 8];
                    #pragma unroll
                    for (int nn = 0; nn < NT; nn++) {
                        const int pl = wn*(NT*8) + nn*8 + tig*2;
                        sE[r*132 + pl]       = acc[m][nn][0] + b0;
                        sE[r*132 + pl+1]     = acc[m][nn][1] + b0;
                        sE[(r+8)*132 + pl]   = acc[m][nn][2] + b1;
                        sE[(r+8)*132 + pl+1] = acc[m][nn][3] + b1;
                    }
                }
            }
            __syncthreads();
            #pragma unroll
            for (int i = 0; i < 4; i++) {
                int idx = tid + i*256;
                int r = idx >> 5, p4 = idx & 31;
                float4 v = *(float4*)&sE[r*132 + p4*4];
                *(float4*)(out0 + (((size_t)b*256 + co0 + p*32 + r) << 12)
                           + pix0 + p4*4) = v;
                if (STATS) {
                    float s  = v.x + v.y + v.z + v.w;
                    float s2 = v.x*v.x + v.y*v.y + v.z*v.z + v.w*v.w;
                    #pragma unroll
                    for (int o = 16; o > 0; o >>= 1) {
                        s  += __shfl_xor_sync(0xffffffffu, s,  o);
                        s2 += __shfl_xor_sync(0xffffffffu, s2, o);
                    }
                    if (lane == 0) {
                        ps[cta*256 + co0 + p*32 + r] = s;
                        pq[cta*256 + co0 + p*32 + r] = s2;
                    }
                }
            }
            __syncthreads();
        }
    } else if (EPI == 1) {
        float sc = 0.f, sc2 = 0.f;
        #pragma unroll
        for (int pass = 0; pass < 2; pass++) {
            if (wn == pass) {
                #pragma unroll
                for (int m = 0; m < 2; m++) {
                    const int r0 = wm*32 + m*16 + g;
                    const float b0 = bias[co0 + r0], b1 = bias[co0 + r0 + 8];
                    #pragma unroll
                    for (int nn = 0; nn < NT; nn++) {
                        const int pl = nn*8 + tig*2;
                        sE[pl*132 + r0]       = acc[m][nn][0] + b0;
                        sE[(pl+1)*132 + r0]   = acc[m][nn][1] + b0;
                        sE[pl*132 + r0+8]     = acc[m][nn][2] + b1;
                        sE[(pl+1)*132 + r0+8] = acc[m][nn][3] + b1;
                    }
                }
            }
            __syncthreads();
            #pragma unroll
            for (int i = 0; i < 8; i++) {
                int idx = tid + i*256;
                int pp = idx >> 5, c4 = idx & 31;
                float4 v = *(float4*)&sE[pp*132 + c4*4];
                *(float4*)(out0 + ((size_t)b*4096 + pix0 + pass*64 + pp)*256
                           + co0 + c4*4) = v;
            }
            if (STATS && tid < 128) {
                #pragma unroll 8
                for (int pp = 0; pp < 64; pp++) {
                    float v = sE[pp*132 + tid];
                    sc += v; sc2 += v*v;
                }
            }
            __syncthreads();
        }
        if (STATS && tid < 128) {
            ps[cta*256 + co0 + tid] = sc;
            pq[cta*256 + co0 + tid] = sc2;
        }
    } else {                                   // EPI 2: offsets + mask (M=32)
        #pragma unroll
        for (int m = 0; m < 2; m++)
            #pragma unroll
            for (int nn = 0; nn < NT; nn++) {
                const int r = m*16 + g;
                const int pl = wn*(NT*8) + nn*8 + tig*2;
                sE[r*132 + pl]       = acc[m][nn][0];
                sE[r*132 + pl+1]     = acc[m][nn][1];
                sE[(r+8)*132 + pl]   = acc[m][nn][2];
                sE[(r+8)*132 + pl+1] = acc[m][nn][3];
            }
        __syncthreads();
        if (tid < 128) {
            const int pix = pix0 + tid;
            #pragma unroll
            for (int r = 0; r < 27; r++) {
                float v = sE[r*132 + tid] + bias[r];
                if (r < 18) out0[((size_t)b*18 + r)*4096 + pix] = v;
                else        out1[((size_t)b*9 + r - 18)*4096 + pix] = 2.f/(1.f + expf(-v));
            }
        }
    }
}

// ---------------- GEMM wrappers -------------------------------------------------
__global__ void __launch_bounds__(256, 2) gemm_conv1(
    const float* __restrict__ A, const float* __restrict__ Bm,
    const float* __restrict__ bias, float* __restrict__ out0,
    float* __restrict__ ps, float* __restrict__ pq)
{
    extern __shared__ float sm[];
    gemm_core<128,1,1,true>(A, Bm, bias, out0, nullptr, ps, pq,
        KFULL, 0, blockIdx.x*128, blockIdx.y*128, blockIdx.z,
        blockIdx.x + (blockIdx.z << 5), sm);
}

__global__ void __launch_bounds__(256, 2) gemm_offmod(
    const float* __restrict__ A, const float* __restrict__ Bm,
    const float* __restrict__ bias,
    float* __restrict__ off, float* __restrict__ msk)
{
    extern __shared__ float sm[];
    gemm_core<32,1,2,false>(A, Bm, bias, off, msk, nullptr, nullptr,
        KFULL, 0, blockIdx.x*128, 0, blockIdx.z,
        blockIdx.x + (blockIdx.z << 5), sm);
}

// y<2: deform GEMM (K=2304, B=col).  y>=2: 1x1 shortcut (K=256, B=xt).
__global__ void __launch_bounds__(256, 2) gemm_dual(
    const float* __restrict__ wdp, const float* __restrict__ col,
    const float* __restrict__ b_d, float* __restrict__ d2,
    float* __restrict__ ps1, float* __restrict__ pq1,
    const float* __restrict__ wds, const float* __restrict__ xt,
    const float* __restrict__ b_ds, float* __restrict__ res,
    float* __restrict__ ps2, float* __restrict__ pq2)
{
    extern __shared__ float sm[];
    const int pix0 = blockIdx.x*128, b = blockIdx.z;
    const int cta = blockIdx.x + (blockIdx.z << 5);
    if (blockIdx.y < 2)
        gemm_core<128,0,0,true>(wdp, col, b_d, d2, nullptr, ps1, pq1,
            KFULL, KFULL, pix0, blockIdx.y*128, b, cta, sm);
    else
        gemm_core<128,0,0,true>(wds, xt, b_ds, res, nullptr, ps2, pq2,
            256, 256, pix0, (blockIdx.y-2)*128, b, cta, sm);
}

// ---------------- stats combine -------------------------------------------------
__global__ __launch_bounds__(256) void bn_combine(const float* __restrict__ ps,
    const float* __restrict__ pq, float* __restrict__ st)
{
    const int c = threadIdx.x;
    float s = 0.f, s2 = 0.f;
    #pragma unroll 8
    for (int j = 0; j < 256; j++) { s += ps[j*256 + c]; s2 += pq[j*256 + c]; }
    const float m = s * (1.f/32768.f);
    const float var = s2 * (1.f/32768.f) - m*m;
    st[c] = m;
    st[256 + c] = rsqrtf(var + 1e-5f);
}

__global__ __launch_bounds__(256) void bn_combine_pair(const float* __restrict__ ps,
    const float* __restrict__ pq, float* __restrict__ st)
{
    const int sel = blockIdx.x;                       // 0: deform, 1: 1x1
    const float* p = ps + (sel+1)*65536;
    const float* q = pq + (sel+1)*65536;
    const int c = threadIdx.x;
    float s = 0.f, s2 = 0.f;
    #pragma unroll 8
    for (int j = 0; j < 256; j++) { s += p[j*256 + c]; s2 += q[j*256 + c]; }
    const float m = s * (1.f/32768.f);
    const float var = s2 * (1.f/32768.f) - m*m;
    st[512 + sel*512 + c] = m;
    st[768 + sel*512 + c] = rsqrtf(var + 1e-5f);
}

// ---------------- merged prep kernel ---------------------------------------------
__global__ __launch_bounds__(256) void prep_all(
    const float* __restrict__ x, float* __restrict__ xt,
    const float* __restrict__ w1, float* __restrict__ w1p,
    const float* __restrict__ w_d, float* __restrict__ wdp,
    const float* __restrict__ w_off, const float* __restrict__ w_mod,
    const float* __restrict__ b_off, const float* __restrict__ b_mod,
    float* __restrict__ wop, float* __restrict__ bp,
    const float* __restrict__ w_ds, float* __restrict__ wds)
{
    __shared__ float tb[32][33];
    const int bx = blockIdx.x;
    if (bx < 8192) {                                  // NCHW->NHWC round of x
        const int b = bx >> 10, cy = (bx >> 7) & 7, cx = bx & 127;
        const int pix0 = cx*32, c0 = cy*32;
        const int tx = threadIdx.x & 31, ty = threadIdx.x >> 5;
        #pragma unroll
        for (int i = 0; i < 4; i++)
            tb[ty + i*8][tx] = f2tff(x[((size_t)b*256 + c0 + ty + i*8)*4096 + pix0 + tx]);
        __syncthreads();
        #pragma unroll
        for (int i = 0; i < 4; i++)
            xt[((size_t)b*4096 + pix0 + ty + i*8)*256 + c0 + tx] = tb[tx][ty + i*8];
    } else if (bx < 8192 + 2304) {                    // permute w1
        int i = (bx - 8192)*256 + threadIdx.x;
        int co = i / KFULL, r = i - co*KFULL;
        int t = r >> 8, ci = r & 255;
        w1p[i] = f2tff(w1[co*KFULL + ci*9 + t]);
    } else if (bx < 8192 + 4608) {                    // permute w_d
        int i = (bx - 8192 - 2304)*256 + threadIdx.x;
        int co = i / KFULL, r = i - co*KFULL;
        int t = r >> 8, ci = r & 255;
        wdp[i] = f2tff(w_d[co*KFULL + ci*9 + t]);
    } else if (bx < 8192 + 4896) {                    // pack offmod
        int i = (bx - 8192 - 4608)*256 + threadIdx.x;
        if (i < 32*KFULL) {
            int o = i / KFULL, r = i - o*KFULL;
            int t = r >> 8, ci = r & 255;
            float v = 0.f;
            if (o < 18)      v = w_off[o*KFULL + ci*9 + t];
            else if (o < 27) v = w_mod[(o-18)*KFULL + ci*9 + t];
            wop[i] = f2tff(v);
        }
        if (i < 27) bp[i] = (i < 18) ? b_off[i] : b_mod[i-18];
    } else {                                          // round w_ds
        int i = (bx - 8192 - 4896)*256 + threadIdx.x;
        wds[i] = f2tff(w_ds[i]);
    }
}

// in-place BN + ReLU + tf32 round on NHWC
__global__ __launch_bounds__(256) void bn_relu_nhwc(float* __restrict__ y,
    const float* __restrict__ st, const float* __restrict__ g, const float* __restrict__ bt)
{
    const int i = blockIdx.x*256 + threadIdx.x;
    const int c = i & 255;
    const float v = (y[i] - st[c]) * st[256 + c] * g[c] + bt[c];
    y[i] = f2tff(fmaxf(v, 0.f));
}

// ---------------- deformable gather on NHWC -> col [b][pix][k] -------------------
__global__ __launch_bounds__(288) void deform_sample(
    const float* __restrict__ y1h, const float* __restrict__ off,
    const float* __restrict__ msk, float* __restrict__ col)
{
    const int p = threadIdx.x >> 5, lane = threadIdx.x & 31;
    const int pix = blockIdx.x, b = blockIdx.y;
    const int ho = pix >> 6, wo = pix & 63;

    const float dy = off[((size_t)b*18 + 2*p    )*4096 + pix];
    const float dx = off[((size_t)b*18 + 2*p + 1)*4096 + pix];
    const float m  = msk[((size_t)b*9 + p)*4096 + pix];
    const float py = (float)(ho - 1 + p/3) + dy;
    const float px = (float)(wo - 1 + p%3) + dx;

    const float y0f = floorf(py), x0f = floorf(px);
    const float ly = py - y0f, lx = px - x0f;
    const int y0 = (int)y0f, x0 = (int)x0f;
    const int y1 = y0 + 1,  x1 = x0 + 1;
    float w00 = (1.f-ly)*(1.f-lx), w01 = (1.f-ly)*lx, w10 = ly*(1.f-lx), w11 = ly*lx;
    const bool vy0 = (y0 >= 0) && (y0 < 64), vy1 = (y1 >= 0) && (y1 < 64);
    const bool vx0 = (x0 >= 0) && (x0 < 64), vx1 = (x1 >= 0) && (x1 < 64);
    if (!(vy0 && vx0)) w00 = 0.f;
    if (!(vy0 && vx1)) w01 = 0.f;
    if (!(vy1 && vx0)) w10 = 0.f;
    if (!(vy1 && vx1)) w11 = 0.f;
    const int yc0 = min(max(y0, 0), 63), yc1 = min(max(y1, 0), 63);
    const int xc0 = min(max(x0, 0), 63), xc1 = min(max(x1, 0), 63);
    w00 *= m; w01 *= m; w10 *= m; w11 *= m;

    const float* base = y1h + (size_t)b*4096*256;
    const float* p00 = base + (size_t)(yc0*64 + xc0)*256 + lane*8;
    const float* p01 = base + (size_t)(yc0*64 + xc1)*256 + lane*8;
    const float* p10 = base + (size_t)(yc1*64 + xc0)*256 + lane*8;
    const float* p11 = base + (size_t)(yc1*64 + xc1)*256 + lane*8;
    float* cp = col + ((size_t)b*4096 + pix)*KFULL + p*256 + lane*8;

    #pragma unroll
    for (int h = 0; h < 2; h++) {
        const float4 a = *(const float4*)(p00 + h*4);
        const float4 c2 = *(const float4*)(p01 + h*4);
        const float4 d = *(const float4*)(p10 + h*4);
        const float4 e = *(const float4*)(p11 + h*4);
        float4 s;
        s.x = f2tff(w00*a.x + w01*c2.x + w10*d.x + w11*e.x);
        s.y = f2tff(w00*a.y + w01*c2.y + w10*d.y + w11*e.y);
        s.z = f2tff(w00*a.z + w01*c2.z + w10*d.z + w11*e.z);
        s.w = f2tff(w00*a.w + w01*c2.w + w10*d.w + w11*e.w);
        *(float4*)(cp + h*4) = s;
    }
}

// ---------------- final: relu( bn2(d2) + bn3(res) ) --------------------------------
__global__ __launch_bounds__(256) void final_fuse(
    const float* __restrict__ d2, const float* __restrict__ res,
    const float* __restrict__ st,
    const float* __restrict__ g2, const float* __restrict__ bt2,
    const float* __restrict__ g3, const float* __restrict__ bt3,
    float* __restrict__ out)
{
    const int i = blockIdx.x*256 + threadIdx.x;
    const int c = (i >> 12) & 255;
    const float a = (d2[i]  - st[512 + c])  * st[768 + c]  * g2[c] + bt2[c];
    const float r = (res[i] - st[1024 + c]) * st[1280 + c] * g3[c] + bt3[c];
    out[i] = fmaxf(a + r, 0.f);
}

// ---------------- launcher -----------------------------------------------------------
extern "C" void kernel_launch(void* const* d_in, const int* in_sizes, int n_in,
                              void* d_out, int out_size)
{
    const float* x     = (const float*)d_in[0];
    const float* w1    = (const float*)d_in[2];
    const float* b1    = (const float*)d_in[3];
    const float* g1    = (const float*)d_in[4];
    const float* bt1   = (const float*)d_in[5];
    const float* w_off = (const float*)d_in[6];
    const float* b_off = (const float*)d_in[7];
    const float* w_mod = (const float*)d_in[8];
    const float* b_mod = (const float*)d_in[9];
    const float* w_d   = (const float*)d_in[10];
    const float* b_d   = (const float*)d_in[11];
    const float* g2    = (const float*)d_in[12];
    const float* bt2   = (const float*)d_in[13];
    const float* w_ds  = (const float*)d_in[14];
    const float* b_ds  = (const float*)d_in[15];
    const float* g3    = (const float*)d_in[16];
    const float* bt3   = (const float*)d_in[17];

    float *xt, *y1h, *d2, *res, *off, *msk, *col, *st, *ps, *pq;
    float *w1p, *wdp, *wop, *wds, *bp;
    cudaGetSymbolAddress((void**)&xt,  g_xt);
    cudaGetSymbolAddress((void**)&y1h, g_y1h);
    cudaGetSymbolAddress((void**)&d2,  g_d2);
    cudaGetSymbolAddress((void**)&res, g_res);
    cudaGetSymbolAddress((void**)&off, g_off);
    cudaGetSymbolAddress((void**)&msk, g_mask);
    cudaGetSymbolAddress((void**)&col, g_col);
    cudaGetSymbolAddress((void**)&st,  g_stats);
    cudaGetSymbolAddress((void**)&ps,  g_ps);
    cudaGetSymbolAddress((void**)&pq,  g_pq);
    cudaGetSymbolAddress((void**)&w1p, g_w1p);
    cudaGetSymbolAddress((void**)&wdp, g_wdp);
    cudaGetSymbolAddress((void**)&wop, g_wop);
    cudaGetSymbolAddress((void**)&wds, g_wds);
    cudaGetSymbolAddress((void**)&bp,  g_bp);

    const int SM128 = 3 * (128*36 + 128*36) * 4;   // 110592
    const int SM32  = 3 * (32*36  + 128*36) * 4;   // 69120
    cudaFuncSetAttribute(gemm_conv1,  cudaFuncAttributeMaxDynamicSharedMemorySize, SM128);
    cudaFuncSetAttribute(gemm_dual,   cudaFuncAttributeMaxDynamicSharedMemorySize, SM128);
    cudaFuncSetAttribute(gemm_offmod, cudaFuncAttributeMaxDynamicSharedMemorySize, SM32);

    // 0) merged prep: NHWC x, all weight permutes/rounds
    prep_all<<<13344, 256>>>(x, xt, w1, w1p, w_d, wdp,
                             w_off, w_mod, b_off, b_mod, wop, bp, w_ds, wds);
    // 1) conv1: implicit 3x3 GEMM -> y1h NHWC raw + fused stats partials
    gemm_conv1<<<dim3(32, 2, BN), 256, SM128>>>(w1p, xt, b1, y1h, ps, pq);
    bn_combine<<<1, 256>>>(ps, pq, st);
    // 2) BN1 + ReLU + round, in place
    bn_relu_nhwc<<<(int)((size_t)BN*HWn*C/256), 256>>>(y1h, st, g1, bt1);
    // 3) offsets + modulation
    gemm_offmod<<<dim3(32, 1, BN), 256, SM32>>>(wop, y1h, bp, off, msk);
    // 4) bilinear gather -> col [b][pix][k]
    deform_sample<<<dim3(HWn, BN), 288>>>(y1h, off, msk, col);
    // 5) deform GEMM + 1x1 shortcut, grid-merged (co-scheduled)
    gemm_dual<<<dim3(32, 4, BN), 256, SM128>>>(
        wdp, col, b_d, d2, ps + 65536, pq + 65536,
        wds, xt,  b_ds, res, ps + 2*65536, pq + 2*65536);
    bn_combine_pair<<<2, 256>>>(ps, pq, st);
    // 6) fused BN2 + BN3 + add + ReLU
    final_fuse<<<BN*C*HWn/256, 256>>>(d2, res, st, g2, bt2, g3, bt3, (float*)d_out);
}

// round 11
// speedup vs baseline: 1.3090x; 1.0512x over previous
#include <cuda_runtime.h>
#include <math.h>
#include <stdint.h>

#define BN 8
#define C 256
#define HWn 4096
#define KFULL 2304

// ---------------- scratch (device globals: allocation-free) ----------------
__device__ float g_xt [(size_t)BN*HWn*C];        // x NHWC, tf32-rounded
__device__ float g_y1h[(size_t)BN*HWn*C];        // conv1 NHWC raw -> (in place) bn+relu rounded
__device__ float g_d2 [(size_t)BN*C*HWn];        // deform conv raw NCHW
__device__ float g_res[(size_t)BN*C*HWn];        // 1x1 raw NCHW
__device__ float g_off[BN*18*HWn];
__device__ float g_mask[BN*9*HWn];
__device__ float g_col[(size_t)BN*HWn*KFULL];    // [b][pix][k=p*256+ci], rounded
__device__ float g_stats[6*256];
__device__ float g_ps[3*256*256];                // [cta][c]
__device__ float g_pq[3*256*256];
__device__ float g_w1p[256*KFULL];
__device__ float g_wdp[256*KFULL];
__device__ float g_wop[32*KFULL];
__device__ float g_wds[256*256];
__device__ float g_bp[32];

// ---------------- helpers -----------------------------------------------------
__device__ __forceinline__ unsigned f2tf(float v) {
    unsigned u; asm("cvt.rna.tf32.f32 %0, %1;" : "=r"(u) : "f"(v)); return u;
}
__device__ __forceinline__ float f2tff(float v) { return __uint_as_float(f2tf(v)); }
__device__ __forceinline__ uint32_t s2u(const void* p) {
    uint32_t a;
    asm("{ .reg .u64 t; cvta.to.shared.u64 t, %1; cvt.u32.u64 %0, t; }" : "=r"(a) : "l"(p));
    return a;
}
__device__ __forceinline__ void cpa16(uint32_t dst, const void* src, bool v) {
    int sz = v ? 16 : 0;
    asm volatile("cp.async.cg.shared.global [%0], [%1], 16, %2;"
                 :: "r"(dst), "l"(src), "r"(sz) : "memory");
}
__device__ __forceinline__ void mma8(float* d, const uint4& a, const uint2& b) {
    asm volatile("mma.sync.aligned.m16n8k8.row.col.f32.tf32.tf32.f32 "
        "{%0,%1,%2,%3}, {%4,%5,%6,%7}, {%8,%9}, {%0,%1,%2,%3};"
        : "+f"(d[0]), "+f"(d[1]), "+f"(d[2]), "+f"(d[3])
        : "r"(a.x), "r"(a.y), "r"(a.z), "r"(a.w), "r"(b.x), "r"(b.y));
}

// ---------------- GEMM core: 128 threads, 64x64 warp tile, 3-stage cp.async ------
// D[M co x 128 pix] = A[co][k] * B[k][pix]; K chunks of 32.
// Warps: WMn x WNn = 2x2 (M=128) or 1x4 (M=32). Warp tile: (M/WMn) co x (128/WNn) pix.
// BMODE 0: B[k][pix] = Bm[(b*4096+pix)*ROWLEN + k]
// BMODE 1: implicit 3x3 im2col of NHWC Bm, k = t*256+ci (zero-fill)
// EPI 0: NCHW out (+bias).  EPI 1: NHWC out (+bias).  EPI 2: offsets/mask.
// STATS: per-channel partials -> ps/pq[cta*256 + c].
template<int M, int BMODE, int EPI, bool STATS>
__device__ __forceinline__ void gemm_core(
    const float* __restrict__ A, const float* __restrict__ Bm,
    const float* __restrict__ bias,
    float* __restrict__ out0, float* __restrict__ out1,
    float* __restrict__ ps, float* __restrict__ pq,
    int Kdim, int ROWLEN, int pix0, int co0, int b, int cta, float* sm)
{
    constexpr int WMn = (M == 128) ? 2 : 1;
    constexpr int WNn = 4 / WMn;
    constexpr int MI  = M / (16 * WMn);      // m16 tiles per warp: 4 or 2
    constexpr int NT  = 128 / (8 * WNn);     // n8 tiles per warp: 8 or 4
    constexpr int APITCH = 36;
    constexpr int ABUF = M * APITCH;
    constexpr int BBUF = 128 * APITCH;
    constexpr int STAGE = ABUF + BBUF;

    const int tid = threadIdx.x, lane = tid & 31, warp = tid >> 5;
    const int wm = warp / WNn, wn = warp % WNn;
    const int g = lane >> 2, tig = lane & 3;
    const uint32_t smu = s2u(sm);

    float acc[MI][NT][4] = {};
    const int nch = Kdim >> 5;

    auto stage = [&](int ic, int buf) {
        const int k0 = ic << 5;
        uint32_t sA = smu + buf * STAGE * 4;
        uint32_t sB = sA + ABUF * 4;
        #pragma unroll
        for (int i = 0; i < M/16; i++) {            // A: M x 32k (M*8 tasks / 128 thr)
            int idx = tid + i*128;
            int row = idx >> 3, kq = idx & 7;
            cpa16(sA + (row*APITCH + kq*4)*4,
                  A + (size_t)(co0+row)*Kdim + k0 + kq*4, true);
        }
        int ty = 0, tx = 0, ci0 = 0;
        if (BMODE == 1) { int t = k0 >> 8; ty = t/3 - 1; tx = t%3 - 1; ci0 = k0 & 255; }
        #pragma unroll
        for (int i = 0; i < 8; i++) {               // B: 32k x 128pix
            int idx = tid + i*128;
            int pp = idx >> 3, kq = idx & 7;
            uint32_t dst = sB + (pp*APITCH + kq*4)*4;
            if (BMODE == 1) {
                int pix = pix0 + pp;
                int py = (pix >> 6) + ty, px = (pix & 63) + tx;
                bool v = (py >= 0) && (py < 64) && (px >= 0) && (px < 64);
                cpa16(dst, Bm + ((size_t)b*4096 + (v ? (py*64+px) : 0))*256
                           + ci0 + kq*4, v);
            } else {
                cpa16(dst, Bm + ((size_t)b*4096 + pix0 + pp)*(size_t)ROWLEN
                           + k0 + kq*4, true);
            }
        }
        asm volatile("cp.async.commit_group;" ::: "memory");
    };

    stage(0, 0);
    stage(1, 1);
    for (int ic = 0; ic < nch; ic++) {
        const int buf = ic % 3;
        if (ic + 2 < nch) {
            stage(ic + 2, (ic + 2) % 3);
            asm volatile("cp.async.wait_group 2;" ::: "memory");
        } else if (ic + 1 < nch) {
            asm volatile("cp.async.wait_group 1;" ::: "memory");
        } else {
            asm volatile("cp.async.wait_group 0;" ::: "memory");
        }
        __syncthreads();
        const float* sA = sm + buf*STAGE;
        const float* sB = sA + ABUF;
        #pragma unroll
        for (int k8 = 0; k8 < 4; k8++) {
            const int kb = k8 * 8;
            uint4 af[MI];
            #pragma unroll
            for (int mi = 0; mi < MI; mi++) {
                const int cw = wm*(MI*16) + mi*16;
                af[mi].x = __float_as_uint(sA[(cw+g  )*APITCH + kb+tig  ]);
                af[mi].y = __float_as_uint(sA[(cw+g+8)*APITCH + kb+tig  ]);
                af[mi].z = __float_as_uint(sA[(cw+g  )*APITCH + kb+tig+4]);
                af[mi].w = __float_as_uint(sA[(cw+g+8)*APITCH + kb+tig+4]);
            }
            #pragma unroll
            for (int nn = 0; nn < NT; nn++) {
                const int pc = wn*(NT*8) + nn*8 + g;
                uint2 bb;
                bb.x = __float_as_uint(sB[pc*APITCH + kb+tig  ]);
                bb.y = __float_as_uint(sB[pc*APITCH + kb+tig+4]);
                #pragma unroll
                for (int mi = 0; mi < MI; mi++)
                    mma8(acc[mi][nn], af[mi], bb);
            }
        }
        __syncthreads();
    }

    // ---- epilogue (reuses smem) ----
    float* sE = sm;
    if (EPI == 0) {                      // NCHW out; 4 passes over 32-co groups
        #pragma unroll
        for (int p = 0; p < 4; p++) {
            if (wm == (p >> 1)) {
                #pragma unroll
                for (int ml = 0; ml < 2; ml++) {
                    const int mi = (p & 1)*2 + ml;
                    const int r = ml*16 + g;
                    const float b0 = bias[co0 + p*32 + r];
                    const float b1 = bias[co0 + p*32 + r + 8];
                    #pragma unroll
                    for (int nn = 0; nn < NT; nn++) {
                        const int pl = wn*(NT*8) + nn*8 + tig*2;
                        sE[r*132 + pl]       = acc[mi][nn][0] + b0;
                        sE[r*132 + pl+1]     = acc[mi][nn][1] + b0;
                        sE[(r+8)*132 + pl]   = acc[mi][nn][2] + b1;
                        sE[(r+8)*132 + pl+1] = acc[mi][nn][3] + b1;
                    }
                }
            }
            __syncthreads();
            #pragma unroll
            for (int i = 0; i < 8; i++) {
                int idx = tid + i*128;
                int r = idx >> 5, p4 = idx & 31;
                float4 v = *(float4*)&sE[r*132 + p4*4];
                *(float4*)(out0 + (((size_t)b*256 + co0 + p*32 + r) << 12)
                           + pix0 + p4*4) = v;
                if (STATS) {
                    float s  = v.x + v.y + v.z + v.w;
                    float s2 = v.x*v.x + v.y*v.y + v.z*v.z + v.w*v.w;
                    #pragma unroll
                    for (int o = 16; o > 0; o >>= 1) {
                        s  += __shfl_xor_sync(0xffffffffu, s,  o);
                        s2 += __shfl_xor_sync(0xffffffffu, s2, o);
                    }
                    if (lane == 0) {
                        ps[cta*256 + co0 + p*32 + r] = s;
                        pq[cta*256 + co0 + p*32 + r] = s2;
                    }
                }
            }
            __syncthreads();
        }
    } else if (EPI == 1) {               // NHWC out; 2 passes over 64-pix halves
        float sc = 0.f, sc2 = 0.f;
        #pragma unroll
        for (int pass = 0; pass < 2; pass++) {
            if (wn == pass) {
                #pragma unroll
                for (int mi = 0; mi < MI; mi++) {
                    const int r0 = wm*(MI*16) + mi*16 + g;
                    const float b0 = bias[co0 + r0], b1 = bias[co0 + r0 + 8];
                    #pragma unroll
                    for (int nn = 0; nn < NT; nn++) {
                        const int pl = nn*8 + tig*2;
                        sE[pl*132 + r0]       = acc[mi][nn][0] + b0;
                        sE[(pl+1)*132 + r0]   = acc[mi][nn][1] + b0;
                        sE[pl*132 + r0+8]     = acc[mi][nn][2] + b1;
                        sE[(pl+1)*132 + r0+8] = acc[mi][nn][3] + b1;
                    }
                }
            }
            __syncthreads();
            #pragma unroll
            for (int i = 0; i < 16; i++) {
                int idx = tid + i*128;
                int pp = idx >> 5, c4 = idx & 31;
                float4 v = *(float4*)&sE[pp*132 + c4*4];
                *(float4*)(out0 + ((size_t)b*4096 + pix0 + pass*64 + pp)*256
                           + co0 + c4*4) = v;
            }
            if (STATS) {
                #pragma unroll 8
                for (int pp = 0; pp < 64; pp++) {
                    float v = sE[pp*132 + tid];
                    sc += v; sc2 += v*v;
                }
            }
            __syncthreads();
        }
        if (STATS) {
            ps[cta*256 + co0 + tid] = sc;
            pq[cta*256 + co0 + tid] = sc2;
        }
    } else {                             // EPI 2: offsets + mask (M=32, WNn=4)
        #pragma unroll
        for (int mi = 0; mi < MI; mi++)
            #pragma unroll
            for (int nn = 0; nn < NT; nn++) {
                const int r = mi*16 + g;
                const int pl = wn*(NT*8) + nn*8 + tig*2;
                sE[r*132 + pl]       = acc[mi][nn][0];
                sE[r*132 + pl+1]     = acc[mi][nn][1];
                sE[(r+8)*132 + pl]   = acc[mi][nn][2];
                sE[(r+8)*132 + pl+1] = acc[mi][nn][3];
            }
        __syncthreads();
        {
            const int pix = pix0 + tid;
            #pragma unroll
            for (int r = 0; r < 27; r++) {
                float v = sE[r*132 + tid] + bias[r];
                if (r < 18) out0[((size_t)b*18 + r)*4096 + pix] = v;
                else        out1[((size_t)b*9 + r - 18)*4096 + pix] = 2.f/(1.f + expf(-v));
            }
        }
    }
}

// ---------------- GEMM wrappers -------------------------------------------------
__global__ void __launch_bounds__(128, 2) gemm_conv1(
    const float* __restrict__ A, const float* __restrict__ Bm,
    const float* __restrict__ bias, float* __restrict__ out0,
    float* __restrict__ ps, float* __restrict__ pq)
{
    extern __shared__ float sm[];
    gemm_core<128,1,1,true>(A, Bm, bias, out0, nullptr, ps, pq,
        KFULL, 0, blockIdx.x*128, blockIdx.y*128, blockIdx.z,
        blockIdx.x + (blockIdx.z << 5), sm);
}

__global__ void __launch_bounds__(128, 2) gemm_offmod(
    const float* __restrict__ A, const float* __restrict__ Bm,
    const float* __restrict__ bias,
    float* __restrict__ off, float* __restrict__ msk)
{
    extern __shared__ float sm[];
    gemm_core<32,1,2,false>(A, Bm, bias, off, msk, nullptr, nullptr,
        KFULL, 0, blockIdx.x*128, 0, blockIdx.z,
        blockIdx.x + (blockIdx.z << 5), sm);
}

// y<2: deform GEMM (K=2304, B=col).  y>=2: 1x1 shortcut (K=256, B=xt).
__global__ void __launch_bounds__(128, 2) gemm_dual(
    const float* __restrict__ wdp, const float* __restrict__ col,
    const float* __restrict__ b_d, float* __restrict__ d2,
    float* __restrict__ ps1, float* __restrict__ pq1,
    const float* __restrict__ wds, const float* __restrict__ xt,
    const float* __restrict__ b_ds, float* __restrict__ res,
    float* __restrict__ ps2, float* __restrict__ pq2)
{
    extern __shared__ float sm[];
    const int pix0 = blockIdx.x*128, b = blockIdx.z;
    const int cta = blockIdx.x + (blockIdx.z << 5);
    if (blockIdx.y < 2)
        gemm_core<128,0,0,true>(wdp, col, b_d, d2, nullptr, ps1, pq1,
            KFULL, KFULL, pix0, blockIdx.y*128, b, cta, sm);
    else
        gemm_core<128,0,0,true>(wds, xt, b_ds, res, nullptr, ps2, pq2,
            256, 256, pix0, (blockIdx.y-2)*128, b, cta, sm);
}

// ---------------- stats combine -------------------------------------------------
__global__ __launch_bounds__(256) void bn_combine(const float* __restrict__ ps,
    const float* __restrict__ pq, float* __restrict__ st)
{
    const int c = threadIdx.x;
    float s = 0.f, s2 = 0.f;
    #pragma unroll 8
    for (int j = 0; j < 256; j++) { s += ps[j*256 + c]; s2 += pq[j*256 + c]; }
    const float m = s * (1.f/32768.f);
    const float var = s2 * (1.f/32768.f) - m*m;
    st[c] = m;
    st[256 + c] = rsqrtf(var + 1e-5f);
}

__global__ __launch_bounds__(256) void bn_combine_pair(const float* __restrict__ ps,
    const float* __restrict__ pq, float* __restrict__ st)
{
    const int sel = blockIdx.x;                       // 0: deform, 1: 1x1
    const float* p = ps + (sel+1)*65536;
    const float* q = pq + (sel+1)*65536;
    const int c = threadIdx.x;
    float s = 0.f, s2 = 0.f;
    #pragma unroll 8
    for (int j = 0; j < 256; j++) { s += p[j*256 + c]; s2 += q[j*256 + c]; }
    const float m = s * (1.f/32768.f);
    const float var = s2 * (1.f/32768.f) - m*m;
    st[512 + sel*512 + c] = m;
    st[768 + sel*512 + c] = rsqrtf(var + 1e-5f);
}

// ---------------- merged prep kernel ---------------------------------------------
__global__ __launch_bounds__(256) void prep_all(
    const float* __restrict__ x, float* __restrict__ xt,
    const float* __restrict__ w1, float* __restrict__ w1p,
    const float* __restrict__ w_d, float* __restrict__ wdp,
    const float* __restrict__ w_off, const float* __restrict__ w_mod,
    const float* __restrict__ b_off, const float* __restrict__ b_mod,
    float* __restrict__ wop, float* __restrict__ bp,
    const float* __restrict__ w_ds, float* __restrict__ wds)
{
    __shared__ float tb[32][33];
    const int bx = blockIdx.x;
    if (bx < 8192) {                                  // NCHW->NHWC round of x
        const int b = bx >> 10, cy = (bx >> 7) & 7, cx = bx & 127;
        const int pix0 = cx*32, c0 = cy*32;
        const int tx = threadIdx.x & 31, ty = threadIdx.x >> 5;
        #pragma unroll
        for (int i = 0; i < 4; i++)
            tb[ty + i*8][tx] = f2tff(x[((size_t)b*256 + c0 + ty + i*8)*4096 + pix0 + tx]);
        __syncthreads();
        #pragma unroll
        for (int i = 0; i < 4; i++)
            xt[((size_t)b*4096 + pix0 + ty + i*8)*256 + c0 + tx] = tb[tx][ty + i*8];
    } else if (bx < 8192 + 2304) {                    // permute w1
        int i = (bx - 8192)*256 + threadIdx.x;
        int co = i / KFULL, r = i - co*KFULL;
        int t = r >> 8, ci = r & 255;
        w1p[i] = f2tff(w1[co*KFULL + ci*9 + t]);
    } else if (bx < 8192 + 4608) {                    // permute w_d
        int i = (bx - 8192 - 2304)*256 + threadIdx.x;
        int co = i / KFULL, r = i - co*KFULL;
        int t = r >> 8, ci = r & 255;
        wdp[i] = f2tff(w_d[co*KFULL + ci*9 + t]);
    } else if (bx < 8192 + 4896) {                    // pack offmod
        int i = (bx - 8192 - 4608)*256 + threadIdx.x;
        if (i < 32*KFULL) {
            int o = i / KFULL, r = i - o*KFULL;
            int t = r >> 8, ci = r & 255;
            float v = 0.f;
            if (o < 18)      v = w_off[o*KFULL + ci*9 + t];
            else if (o < 27) v = w_mod[(o-18)*KFULL + ci*9 + t];
            wop[i] = f2tff(v);
        }
        if (i < 27) bp[i] = (i < 18) ? b_off[i] : b_mod[i-18];
    } else {                                          // round w_ds
        int i = (bx - 8192 - 4896)*256 + threadIdx.x;
        wds[i] = f2tff(w_ds[i]);
    }
}

// in-place BN + ReLU + tf32 round on NHWC
__global__ __launch_bounds__(256) void bn_relu_nhwc(float* __restrict__ y,
    const float* __restrict__ st, const float* __restrict__ g, const float* __restrict__ bt)
{
    const int i = blockIdx.x*256 + threadIdx.x;
    const int c = i & 255;
    const float v = (y[i] - st[c]) * st[256 + c] * g[c] + bt[c];
    y[i] = f2tff(fmaxf(v, 0.f));
}

// ---------------- deformable gather on NHWC -> col [b][pix][k] -------------------
__global__ __launch_bounds__(288) void deform_sample(
    const float* __restrict__ y1h, const float* __restrict__ off,
    const float* __restrict__ msk, float* __restrict__ col)
{
    const int p = threadIdx.x >> 5, lane = threadIdx.x & 31;
    const int pix = blockIdx.x, b = blockIdx.y;
    const int ho = pix >> 6, wo = pix & 63;

    const float dy = off[((size_t)b*18 + 2*p    )*4096 + pix];
    const float dx = off[((size_t)b*18 + 2*p + 1)*4096 + pix];
    const float m  = msk[((size_t)b*9 + p)*4096 + pix];
    const float py = (float)(ho - 1 + p/3) + dy;
    const float px = (float)(wo - 1 + p%3) + dx;

    const float y0f = floorf(py), x0f = floorf(px);
    const float ly = py - y0f, lx = px - x0f;
    const int y0 = (int)y0f, x0 = (int)x0f;
    const int y1 = y0 + 1,  x1 = x0 + 1;
    float w00 = (1.f-ly)*(1.f-lx), w01 = (1.f-ly)*lx, w10 = ly*(1.f-lx), w11 = ly*lx;
    const bool vy0 = (y0 >= 0) && (y0 < 64), vy1 = (y1 >= 0) && (y1 < 64);
    const bool vx0 = (x0 >= 0) && (x0 < 64), vx1 = (x1 >= 0) && (x1 < 64);
    if (!(vy0 && vx0)) w00 = 0.f;
    if (!(vy0 && vx1)) w01 = 0.f;
    if (!(vy1 && vx0)) w10 = 0.f;
    if (!(vy1 && vx1)) w11 = 0.f;
    const int yc0 = min(max(y0, 0), 63), yc1 = min(max(y1, 0), 63);
    const int xc0 = min(max(x0, 0), 63), xc1 = min(max(x1, 0), 63);
    w00 *= m; w01 *= m; w10 *= m; w11 *= m;

    const float* base = y1h + (size_t)b*4096*256;
    const float* p00 = base + (size_t)(yc0*64 + xc0)*256 + lane*8;
    const float* p01 = base + (size_t)(yc0*64 + xc1)*256 + lane*8;
    const float* p10 = base + (size_t)(yc1*64 + xc0)*256 + lane*8;
    const float* p11 = base + (size_t)(yc1*64 + xc1)*256 + lane*8;
    float* cp = col + ((size_t)b*4096 + pix)*KFULL + p*256 + lane*8;

    #pragma unroll
    for (int h = 0; h < 2; h++) {
        const float4 a = *(const float4*)(p00 + h*4);
        const float4 c2 = *(const float4*)(p01 + h*4);
        const float4 d = *(const float4*)(p10 + h*4);
        const float4 e = *(const float4*)(p11 + h*4);
        float4 s;
        s.x = f2tff(w00*a.x + w01*c2.x + w10*d.x + w11*e.x);
        s.y = f2tff(w00*a.y + w01*c2.y + w10*d.y + w11*e.y);
        s.z = f2tff(w00*a.z + w01*c2.z + w10*d.z + w11*e.z);
        s.w = f2tff(w00*a.w + w01*c2.w + w10*d.w + w11*e.w);
        *(float4*)(cp + h*4) = s;
    }
}

// ---------------- final: relu( bn2(d2) + bn3(res) ) --------------------------------
__global__ __launch_bounds__(256) void final_fuse(
    const float* __restrict__ d2, const float* __restrict__ res,
    const float* __restrict__ st,
    const float* __restrict__ g2, const float* __restrict__ bt2,
    const float* __restrict__ g3, const float* __restrict__ bt3,
    float* __restrict__ out)
{
    const int i = blockIdx.x*256 + threadIdx.x;
    const int c = (i >> 12) & 255;
    const float a = (d2[i]  - st[512 + c])  * st[768 + c]  * g2[c] + bt2[c];
    const float r = (res[i] - st[1024 + c]) * st[1280 + c] * g3[c] + bt3[c];
    out[i] = fmaxf(a + r, 0.f);
}

// ---------------- launcher -----------------------------------------------------------
extern "C" void kernel_launch(void* const* d_in, const int* in_sizes, int n_in,
                              void* d_out, int out_size)
{
    const float* x     = (const float*)d_in[0];
    const float* w1    = (const float*)d_in[2];
    const float* b1    = (const float*)d_in[3];
    const float* g1    = (const float*)d_in[4];
    const float* bt1   = (const float*)d_in[5];
    const float* w_off = (const float*)d_in[6];
    const float* b_off = (const float*)d_in[7];
    const float* w_mod = (const float*)d_in[8];
    const float* b_mod = (const float*)d_in[9];
    const float* w_d   = (const float*)d_in[10];
    const float* b_d   = (const float*)d_in[11];
    const float* g2    = (const float*)d_in[12];
    const float* bt2   = (const float*)d_in[13];
    const float* w_ds  = (const float*)d_in[14];
    const float* b_ds  = (const float*)d_in[15];
    const float* g3    = (const float*)d_in[16];
    const float* bt3   = (const float*)d_in[17];

    float *xt, *y1h, *d2, *res, *off, *msk, *col, *st, *ps, *pq;
    float *w1p, *wdp, *wop, *wds, *bp;
    cudaGetSymbolAddress((void**)&xt,  g_xt);
    cudaGetSymbolAddress((void**)&y1h, g_y1h);
    cudaGetSymbolAddress((void**)&d2,  g_d2);
    cudaGetSymbolAddress((void**)&res, g_res);
    cudaGetSymbolAddress((void**)&off, g_off);
    cudaGetSymbolAddress((void**)&msk, g_mask);
    cudaGetSymbolAddress((void**)&col, g_col);
    cudaGetSymbolAddress((void**)&st,  g_stats);
    cudaGetSymbolAddress((void**)&ps,  g_ps);
    cudaGetSymbolAddress((void**)&pq,  g_pq);
    cudaGetSymbolAddress((void**)&w1p, g_w1p);
    cudaGetSymbolAddress((void**)&wdp, g_wdp);
    cudaGetSymbolAddress((void**)&wop, g_wop);
    cudaGetSymbolAddress((void**)&wds, g_wds);
    cudaGetSymbolAddress((void**)&bp,  g_bp);

    const int SM128 = 3 * (128*36 + 128*36) * 4;   // 110592
    const int SM32  = 3 * (32*36  + 128*36) * 4;   // 69120
    cudaFuncSetAttribute(gemm_conv1,  cudaFuncAttributeMaxDynamicSharedMemorySize, SM128);
    cudaFuncSetAttribute(gemm_dual,   cudaFuncAttributeMaxDynamicSharedMemorySize, SM128);
    cudaFuncSetAttribute(gemm_offmod, cudaFuncAttributeMaxDynamicSharedMemorySize, SM32);

    // 0) merged prep: NHWC x, all weight permutes/rounds
    prep_all<<<13344, 256>>>(x, xt, w1, w1p, w_d, wdp,
                             w_off, w_mod, b_off, b_mod, wop, bp, w_ds, wds);
    // 1) conv1: implicit 3x3 GEMM -> y1h NHWC raw + fused stats partials
    gemm_conv1<<<dim3(32, 2, BN), 128, SM128>>>(w1p, xt, b1, y1h, ps, pq);
    bn_combine<<<1, 256>>>(ps, pq, st);
    // 2) BN1 + ReLU + round, in place
    bn_relu_nhwc<<<(int)((size_t)BN*HWn*C/256), 256>>>(y1h, st, g1, bt1);
    // 3) offsets + modulation
    gemm_offmod<<<dim3(32, 1, BN), 128, SM32>>>(wop, y1h, bp, off, msk);
    // 4) bilinear gather -> col [b][pix][k]
    deform_sample<<<dim3(HWn, BN), 288>>>(y1h, off, msk, col);
    // 5) deform GEMM + 1x1 shortcut, grid-merged (co-scheduled)
    gemm_dual<<<dim3(32, 4, BN), 128, SM128>>>(
        wdp, col, b_d, d2, ps + 65536, pq + 65536,
        wds, xt,  b_ds, res, ps + 2*65536, pq + 2*65536);
    bn_combine_pair<<<2, 256>>>(ps, pq, st);
    // 6) fused BN2 + BN3 + add + ReLU
    final_fuse<<<BN*C*HWn/256, 256>>>(d2, res, st, g2, bt2, g3, bt3, (float*)d_out);
}

// round 12
// speedup vs baseline: 1.3366x; 1.0211x over previous
#include <cuda_runtime.h>
#include <math.h>
#include <stdint.h>

#define BN 8
#define C 256
#define HWn 4096
#define KFULL 2304

// ---------------- scratch (device globals: allocation-free) ----------------
__device__ float g_xt [(size_t)BN*HWn*C];        // x NHWC, tf32-rounded
__device__ float g_y1h[(size_t)BN*HWn*C];        // conv1 NHWC raw -> (in place) bn+relu rounded
__device__ float g_d2 [(size_t)BN*C*HWn];        // deform conv raw NCHW
__device__ float g_res[(size_t)BN*C*HWn];        // 1x1 raw NCHW
__device__ float g_off[BN*18*HWn];
__device__ float g_mask[BN*9*HWn];
__device__ float g_col[(size_t)BN*HWn*KFULL];    // [b][pix][k=p*256+ci], rounded
__device__ float g_stats[6*256];
__device__ float g_ps[3*256*256];                // [cta][c]
__device__ float g_pq[3*256*256];
__device__ float g_w1p[256*KFULL];
__device__ float g_wdp[256*KFULL];
__device__ float g_wop[32*KFULL];
__device__ float g_wds[256*256];
__device__ float g_bp[32];

// ---------------- helpers -----------------------------------------------------
__device__ __forceinline__ unsigned f2tf(float v) {
    unsigned u; asm("cvt.rna.tf32.f32 %0, %1;" : "=r"(u) : "f"(v)); return u;
}
__device__ __forceinline__ float f2tff(float v) { return __uint_as_float(f2tf(v)); }
__device__ __forceinline__ uint32_t s2u(const void* p) {
    uint32_t a;
    asm("{ .reg .u64 t; cvta.to.shared.u64 t, %1; cvt.u32.u64 %0, t; }" : "=r"(a) : "l"(p));
    return a;
}
__device__ __forceinline__ void cpa16(uint32_t dst, const void* src, bool v) {
    int sz = v ? 16 : 0;
    asm volatile("cp.async.cg.shared.global [%0], [%1], 16, %2;"
                 :: "r"(dst), "l"(src), "r"(sz) : "memory");
}
__device__ __forceinline__ void mma8(float* d, const uint4& a, const uint2& b) {
    asm volatile("mma.sync.aligned.m16n8k8.row.col.f32.tf32.tf32.f32 "
        "{%0,%1,%2,%3}, {%4,%5,%6,%7}, {%8,%9}, {%0,%1,%2,%3};"
        : "+f"(d[0]), "+f"(d[1]), "+f"(d[2]), "+f"(d[3])
        : "r"(a.x), "r"(a.y), "r"(a.z), "r"(a.w), "r"(b.x), "r"(b.y));
}

// ---------------- GEMM core: 128 threads, 64x64 warp tile, 3-stage cp.async ------
// Single-barrier pipeline: wait(1); sync; stage(ic+2); compute(ic).
// Invariant at top of iter ic: outstanding groups = {chunk ic, chunk ic+1}
// (groups past K-end are empty but still committed). stage(ic+2) writes buffer
// (ic+2)%3 == (ic-1)%3, freed by the barrier this iteration.
template<int M, int BMODE, int EPI, bool STATS>
__device__ __forceinline__ void gemm_core(
    const float* __restrict__ A, const float* __restrict__ Bm,
    const float* __restrict__ bias,
    float* __restrict__ out0, float* __restrict__ out1,
    float* __restrict__ ps, float* __restrict__ pq,
    int Kdim, int ROWLEN, int pix0, int co0, int b, int cta, float* sm)
{
    constexpr int WMn = (M == 128) ? 2 : 1;
    constexpr int WNn = 4 / WMn;
    constexpr int MI  = M / (16 * WMn);      // m16 tiles per warp: 4 or 2
    constexpr int NT  = 128 / (8 * WNn);     // n8 tiles per warp: 8 or 4
    constexpr int APITCH = 36;
    constexpr int ABUF = M * APITCH;
    constexpr int BBUF = 128 * APITCH;
    constexpr int STAGE = ABUF + BBUF;

    const int tid = threadIdx.x, lane = tid & 31, warp = tid >> 5;
    const int wm = warp / WNn, wn = warp % WNn;
    const int g = lane >> 2, tig = lane & 3;
    const uint32_t smu = s2u(sm);

    float acc[MI][NT][4] = {};
    const int nch = Kdim >> 5;

    auto stage = [&](int ic) {
        if (ic < nch) {
            const int buf = ic % 3;
            const int k0 = ic << 5;
            uint32_t sA = smu + buf * STAGE * 4;
            uint32_t sB = sA + ABUF * 4;
            #pragma unroll
            for (int i = 0; i < M/16; i++) {            // A: M x 32k
                int idx = tid + i*128;
                int row = idx >> 3, kq = idx & 7;
                cpa16(sA + (row*APITCH + kq*4)*4,
                      A + (size_t)(co0+row)*Kdim + k0 + kq*4, true);
            }
            int ty = 0, tx = 0, ci0 = 0;
            if (BMODE == 1) { int t = k0 >> 8; ty = t/3 - 1; tx = t%3 - 1; ci0 = k0 & 255; }
            #pragma unroll
            for (int i = 0; i < 8; i++) {               // B: 32k x 128pix
                int idx = tid + i*128;
                int pp = idx >> 3, kq = idx & 7;
                uint32_t dst = sB + (pp*APITCH + kq*4)*4;
                if (BMODE == 1) {
                    int pix = pix0 + pp;
                    int py = (pix >> 6) + ty, px = (pix & 63) + tx;
                    bool v = (py >= 0) && (py < 64) && (px >= 0) && (px < 64);
                    cpa16(dst, Bm + ((size_t)b*4096 + (v ? (py*64+px) : 0))*256
                               + ci0 + kq*4, v);
                } else {
                    cpa16(dst, Bm + ((size_t)b*4096 + pix0 + pp)*(size_t)ROWLEN
                               + k0 + kq*4, true);
                }
            }
        }
        asm volatile("cp.async.commit_group;" ::: "memory");
    };

    stage(0);
    stage(1);
    for (int ic = 0; ic < nch; ic++) {
        const int buf = ic % 3;
        asm volatile("cp.async.wait_group 1;" ::: "memory");
        __syncthreads();
        stage(ic + 2);
        const float* sA = sm + buf*STAGE;
        const float* sB = sA + ABUF;
        #pragma unroll
        for (int k8 = 0; k8 < 4; k8++) {
            const int kb = k8 * 8;
            uint4 af[MI];
            #pragma unroll
            for (int mi = 0; mi < MI; mi++) {
                const int cw = wm*(MI*16) + mi*16;
                af[mi].x = __float_as_uint(sA[(cw+g  )*APITCH + kb+tig  ]);
                af[mi].y = __float_as_uint(sA[(cw+g+8)*APITCH + kb+tig  ]);
                af[mi].z = __float_as_uint(sA[(cw+g  )*APITCH + kb+tig+4]);
                af[mi].w = __float_as_uint(sA[(cw+g+8)*APITCH + kb+tig+4]);
            }
            #pragma unroll
            for (int nn = 0; nn < NT; nn++) {
                const int pc = wn*(NT*8) + nn*8 + g;
                uint2 bb;
                bb.x = __float_as_uint(sB[pc*APITCH + kb+tig  ]);
                bb.y = __float_as_uint(sB[pc*APITCH + kb+tig+4]);
                #pragma unroll
                for (int mi = 0; mi < MI; mi++)
                    mma8(acc[mi][nn], af[mi], bb);
            }
        }
    }
    __syncthreads();   // epilogue aliases buf0: make sure all warps left mainloop

    // ---- epilogue (reuses smem) ----
    float* sE = sm;
    if (EPI == 0) {                      // NCHW out; 4 passes over 32-co groups
        #pragma unroll
        for (int p = 0; p < 4; p++) {
            if (wm == (p >> 1)) {
                #pragma unroll
                for (int ml = 0; ml < 2; ml++) {
                    const int mi = (p & 1)*2 + ml;
                    const int r = ml*16 + g;
                    const float b0 = bias[co0 + p*32 + r];
                    const float b1 = bias[co0 + p*32 + r + 8];
                    #pragma unroll
                    for (int nn = 0; nn < NT; nn++) {
                        const int pl = wn*(NT*8) + nn*8 + tig*2;
                        sE[r*132 + pl]       = acc[mi][nn][0] + b0;
                        sE[r*132 + pl+1]     = acc[mi][nn][1] + b0;
                        sE[(r+8)*132 + pl]   = acc[mi][nn][2] + b1;
                        sE[(r+8)*132 + pl+1] = acc[mi][nn][3] + b1;
                    }
                }
            }
            __syncthreads();
            #pragma unroll
            for (int i = 0; i < 8; i++) {
                int idx = tid + i*128;
                int r = idx >> 5, p4 = idx & 31;
                float4 v = *(float4*)&sE[r*132 + p4*4];
                *(float4*)(out0 + (((size_t)b*256 + co0 + p*32 + r) << 12)
                           + pix0 + p4*4) = v;
                if (STATS) {
                    float s  = v.x + v.y + v.z + v.w;
                    float s2 = v.x*v.x + v.y*v.y + v.z*v.z + v.w*v.w;
                    #pragma unroll
                    for (int o = 16; o > 0; o >>= 1) {
                        s  += __shfl_xor_sync(0xffffffffu, s,  o);
                        s2 += __shfl_xor_sync(0xffffffffu, s2, o);
                    }
                    if (lane == 0) {
                        ps[cta*256 + co0 + p*32 + r] = s;
                        pq[cta*256 + co0 + p*32 + r] = s2;
                    }
                }
            }
            __syncthreads();
        }
    } else if (EPI == 1) {               // NHWC out; 2 passes over 64-pix halves
        float sc = 0.f, sc2 = 0.f;
        #pragma unroll
        for (int pass = 0; pass < 2; pass++) {
            if (wn == pass) {
                #pragma unroll
                for (int mi = 0; mi < MI; mi++) {
                    const int r0 = wm*(MI*16) + mi*16 + g;
                    const float b0 = bias[co0 + r0], b1 = bias[co0 + r0 + 8];
                    #pragma unroll
                    for (int nn = 0; nn < NT; nn++) {
                        const int pl = nn*8 + tig*2;
                        sE[pl*132 + r0]       = acc[mi][nn][0] + b0;
                        sE[(pl+1)*132 + r0]   = acc[mi][nn][1] + b0;
                        sE[pl*132 + r0+8]     = acc[mi][nn][2] + b1;
                        sE[(pl+1)*132 + r0+8] = acc[mi][nn][3] + b1;
                    }
                }
            }
            __syncthreads();
            #pragma unroll
            for (int i = 0; i < 16; i++) {
                int idx = tid + i*128;
                int pp = idx >> 5, c4 = idx & 31;
                float4 v = *(float4*)&sE[pp*132 + c4*4];
                *(float4*)(out0 + ((size_t)b*4096 + pix0 + pass*64 + pp)*256
                           + co0 + c4*4) = v;
            }
            if (STATS) {
                #pragma unroll 8
                for (int pp = 0; pp < 64; pp++) {
                    float v = sE[pp*132 + tid];
                    sc += v; sc2 += v*v;
                }
            }
            __syncthreads();
        }
        if (STATS) {
            ps[cta*256 + co0 + tid] = sc;
            pq[cta*256 + co0 + tid] = sc2;
        }
    } else {                             // EPI 2: offsets + mask (M=32, WNn=4)
        #pragma unroll
        for (int mi = 0; mi < MI; mi++)
            #pragma unroll
            for (int nn = 0; nn < NT; nn++) {
                const int r = mi*16 + g;
                const int pl = wn*(NT*8) + nn*8 + tig*2;
                sE[r*132 + pl]       = acc[mi][nn][0];
                sE[r*132 + pl+1]     = acc[mi][nn][1];
                sE[(r+8)*132 + pl]   = acc[mi][nn][2];
                sE[(r+8)*132 + pl+1] = acc[mi][nn][3];
            }
        __syncthreads();
        {
            const int pix = pix0 + tid;
            #pragma unroll
            for (int r = 0; r < 27; r++) {
                float v = sE[r*132 + tid] + bias[r];
                if (r < 18) out0[((size_t)b*18 + r)*4096 + pix] = v;
                else        out1[((size_t)b*9 + r - 18)*4096 + pix] = 2.f/(1.f + expf(-v));
            }
        }
    }
}

// ---------------- GEMM wrappers -------------------------------------------------
__global__ void __launch_bounds__(128, 2) gemm_conv1(
    const float* __restrict__ A, const float* __restrict__ Bm,
    const float* __restrict__ bias, float* __restrict__ out0,
    float* __restrict__ ps, float* __restrict__ pq)
{
    extern __shared__ float sm[];
    gemm_core<128,1,1,true>(A, Bm, bias, out0, nullptr, ps, pq,
        KFULL, 0, blockIdx.x*128, blockIdx.y*128, blockIdx.z,
        blockIdx.x + (blockIdx.z << 5), sm);
}

__global__ void __launch_bounds__(128, 2) gemm_offmod(
    const float* __restrict__ A, const float* __restrict__ Bm,
    const float* __restrict__ bias,
    float* __restrict__ off, float* __restrict__ msk)
{
    extern __shared__ float sm[];
    gemm_core<32,1,2,false>(A, Bm, bias, off, msk, nullptr, nullptr,
        KFULL, 0, blockIdx.x*128, 0, blockIdx.z,
        blockIdx.x + (blockIdx.z << 5), sm);
}

// y<2: deform GEMM (K=2304, B=col).  y>=2: 1x1 shortcut (K=256, B=xt).
__global__ void __launch_bounds__(128, 2) gemm_dual(
    const float* __restrict__ wdp, const float* __restrict__ col,
    const float* __restrict__ b_d, float* __restrict__ d2,
    float* __restrict__ ps1, float* __restrict__ pq1,
    const float* __restrict__ wds, const float* __restrict__ xt,
    const float* __restrict__ b_ds, float* __restrict__ res,
    float* __restrict__ ps2, float* __restrict__ pq2)
{
    extern __shared__ float sm[];
    const int pix0 = blockIdx.x*128, b = blockIdx.z;
    const int cta = blockIdx.x + (blockIdx.z << 5);
    if (blockIdx.y < 2)
        gemm_core<128,0,0,true>(wdp, col, b_d, d2, nullptr, ps1, pq1,
            KFULL, KFULL, pix0, blockIdx.y*128, b, cta, sm);
    else
        gemm_core<128,0,0,true>(wds, xt, b_ds, res, nullptr, ps2, pq2,
            256, 256, pix0, (blockIdx.y-2)*128, b, cta, sm);
}

// ---------------- stats combine -------------------------------------------------
__global__ __launch_bounds__(256) void bn_combine(const float* __restrict__ ps,
    const float* __restrict__ pq, float* __restrict__ st)
{
    const int c = threadIdx.x;
    float s = 0.f, s2 = 0.f;
    #pragma unroll 8
    for (int j = 0; j < 256; j++) { s += ps[j*256 + c]; s2 += pq[j*256 + c]; }
    const float m = s * (1.f/32768.f);
    const float var = s2 * (1.f/32768.f) - m*m;
    st[c] = m;
    st[256 + c] = rsqrtf(var + 1e-5f);
}

__global__ __launch_bounds__(256) void bn_combine_pair(const float* __restrict__ ps,
    const float* __restrict__ pq, float* __restrict__ st)
{
    const int sel = blockIdx.x;                       // 0: deform, 1: 1x1
    const float* p = ps + (sel+1)*65536;
    const float* q = pq + (sel+1)*65536;
    const int c = threadIdx.x;
    float s = 0.f, s2 = 0.f;
    #pragma unroll 8
    for (int j = 0; j < 256; j++) { s += p[j*256 + c]; s2 += q[j*256 + c]; }
    const float m = s * (1.f/32768.f);
    const float var = s2 * (1.f/32768.f) - m*m;
    st[512 + sel*512 + c] = m;
    st[768 + sel*512 + c] = rsqrtf(var + 1e-5f);
}

// ---------------- merged prep kernel ---------------------------------------------
__global__ __launch_bounds__(256) void prep_all(
    const float* __restrict__ x, float* __restrict__ xt,
    const float* __restrict__ w1, float* __restrict__ w1p,
    const float* __restrict__ w_d, float* __restrict__ wdp,
    const float* __restrict__ w_off, const float* __restrict__ w_mod,
    const float* __restrict__ b_off, const float* __restrict__ b_mod,
    float* __restrict__ wop, float* __restrict__ bp,
    const float* __restrict__ w_ds, float* __restrict__ wds)
{
    __shared__ float tb[32][33];
    const int bx = blockIdx.x;
    if (bx < 8192) {                                  // NCHW->NHWC round of x
        const int b = bx >> 10, cy = (bx >> 7) & 7, cx = bx & 127;
        const int pix0 = cx*32, c0 = cy*32;
        const int tx = threadIdx.x & 31, ty = threadIdx.x >> 5;
        #pragma unroll
        for (int i = 0; i < 4; i++)
            tb[ty + i*8][tx] = f2tff(x[((size_t)b*256 + c0 + ty + i*8)*4096 + pix0 + tx]);
        __syncthreads();
        #pragma unroll
        for (int i = 0; i < 4; i++)
            xt[((size_t)b*4096 + pix0 + ty + i*8)*256 + c0 + tx] = tb[tx][ty + i*8];
    } else if (bx < 8192 + 2304) {                    // permute w1
        int i = (bx - 8192)*256 + threadIdx.x;
        int co = i / KFULL, r = i - co*KFULL;
        int t = r >> 8, ci = r & 255;
        w1p[i] = f2tff(w1[co*KFULL + ci*9 + t]);
    } else if (bx < 8192 + 4608) {                    // permute w_d
        int i = (bx - 8192 - 2304)*256 + threadIdx.x;
        int co = i / KFULL, r = i - co*KFULL;
        int t = r >> 8, ci = r & 255;
        wdp[i] = f2tff(w_d[co*KFULL + ci*9 + t]);
    } else if (bx < 8192 + 4896) {                    // pack offmod
        int i = (bx - 8192 - 4608)*256 + threadIdx.x;
        if (i < 32*KFULL) {
            int o = i / KFULL, r = i - o*KFULL;
            int t = r >> 8, ci = r & 255;
            float v = 0.f;
            if (o < 18)      v = w_off[o*KFULL + ci*9 + t];
            else if (o < 27) v = w_mod[(o-18)*KFULL + ci*9 + t];
            wop[i] = f2tff(v);
        }
        if (i < 27) bp[i] = (i < 18) ? b_off[i] : b_mod[i-18];
    } else {                                          // round w_ds
        int i = (bx - 8192 - 4896)*256 + threadIdx.x;
        wds[i] = f2tff(w_ds[i]);
    }
}

// in-place BN + ReLU + tf32 round on NHWC
__global__ __launch_bounds__(256) void bn_relu_nhwc(float* __restrict__ y,
    const float* __restrict__ st, const float* __restrict__ g, const float* __restrict__ bt)
{
    const int i = blockIdx.x*256 + threadIdx.x;
    const int c = i & 255;
    const float v = (y[i] - st[c]) * st[256 + c] * g[c] + bt[c];
    y[i] = f2tff(fmaxf(v, 0.f));
}

// ---------------- deformable gather on NHWC -> col [b][pix][k] -------------------
__global__ __launch_bounds__(288) void deform_sample(
    const float* __restrict__ y1h, const float* __restrict__ off,
    const float* __restrict__ msk, float* __restrict__ col)
{
    const int p = threadIdx.x >> 5, lane = threadIdx.x & 31;
    const int pix = blockIdx.x, b = blockIdx.y;
    const int ho = pix >> 6, wo = pix & 63;

    const float dy = off[((size_t)b*18 + 2*p    )*4096 + pix];
    const float dx = off[((size_t)b*18 + 2*p + 1)*4096 + pix];
    const float m  = msk[((size_t)b*9 + p)*4096 + pix];
    const float py = (float)(ho - 1 + p/3) + dy;
    const float px = (float)(wo - 1 + p%3) + dx;

    const float y0f = floorf(py), x0f = floorf(px);
    const float ly = py - y0f, lx = px - x0f;
    const int y0 = (int)y0f, x0 = (int)x0f;
    const int y1 = y0 + 1,  x1 = x0 + 1;
    float w00 = (1.f-ly)*(1.f-lx), w01 = (1.f-ly)*lx, w10 = ly*(1.f-lx), w11 = ly*lx;
    const bool vy0 = (y0 >= 0) && (y0 < 64), vy1 = (y1 >= 0) && (y1 < 64);
    const bool vx0 = (x0 >= 0) && (x0 < 64), vx1 = (x1 >= 0) && (x1 < 64);
    if (!(vy0 && vx0)) w00 = 0.f;
    if (!(vy0 && vx1)) w01 = 0.f;
    if (!(vy1 && vx0)) w10 = 0.f;
    if (!(vy1 && vx1)) w11 = 0.f;
    const int yc0 = min(max(y0, 0), 63), yc1 = min(max(y1, 0), 63);
    const int xc0 = min(max(x0, 0), 63), xc1 = min(max(x1, 0), 63);
    w00 *= m; w01 *= m; w10 *= m; w11 *= m;

    const float* base = y1h + (size_t)b*4096*256;
    const float* p00 = base + (size_t)(yc0*64 + xc0)*256 + lane*8;
    const float* p01 = base + (size_t)(yc0*64 + xc1)*256 + lane*8;
    const float* p10 = base + (size_t)(yc1*64 + xc0)*256 + lane*8;
    const float* p11 = base + (size_t)(yc1*64 + xc1)*256 + lane*8;
    float* cp = col + ((size_t)b*4096 + pix)*KFULL + p*256 + lane*8;

    #pragma unroll
    for (int h = 0; h < 2; h++) {
        const float4 a = *(const float4*)(p00 + h*4);
        const float4 c2 = *(const float4*)(p01 + h*4);
        const float4 d = *(const float4*)(p10 + h*4);
        const float4 e = *(const float4*)(p11 + h*4);
        float4 s;
        s.x = f2tff(w00*a.x + w01*c2.x + w10*d.x + w11*e.x);
        s.y = f2tff(w00*a.y + w01*c2.y + w10*d.y + w11*e.y);
        s.z = f2tff(w00*a.z + w01*c2.z + w10*d.z + w11*e.z);
        s.w = f2tff(w00*a.w + w01*c2.w + w10*d.w + w11*e.w);
        *(float4*)(cp + h*4) = s;
    }
}

// ---------------- final: relu( bn2(d2) + bn3(res) ), float4 ------------------------
__global__ __launch_bounds__(256) void final_fuse(
    const float* __restrict__ d2, const float* __restrict__ res,
    const float* __restrict__ st,
    const float* __restrict__ g2, const float* __restrict__ bt2,
    const float* __restrict__ g3, const float* __restrict__ bt3,
    float* __restrict__ out)
{
    const int i4 = blockIdx.x*256 + threadIdx.x;     // float4 index
    const int c = (i4 >> 10) & 255;                  // (i4*4 >> 12) & 255
    const float a2 = st[768 + c]  * g2[c];
    const float a3 = st[1280 + c] * g3[c];
    const float k2 = bt2[c] - st[512 + c]  * a2;
    const float k3 = bt3[c] - st[1024 + c] * a3;
    const float4 dv = *(const float4*)(d2  + (size_t)i4*4);
    const float4 rv = *(const float4*)(res + (size_t)i4*4);
    float4 o;
    o.x = fmaxf(dv.x*a2 + k2 + rv.x*a3 + k3, 0.f);
    o.y = fmaxf(dv.y*a2 + k2 + rv.y*a3 + k3, 0.f);
    o.z = fmaxf(dv.z*a2 + k2 + rv.z*a3 + k3, 0.f);
    o.w = fmaxf(dv.w*a2 + k2 + rv.w*a3 + k3, 0.f);
    *(float4*)(out + (size_t)i4*4) = o;
}

// ---------------- launcher -----------------------------------------------------------
extern "C" void kernel_launch(void* const* d_in, const int* in_sizes, int n_in,
                              void* d_out, int out_size)
{
    const float* x     = (const float*)d_in[0];
    const float* w1    = (const float*)d_in[2];
    const float* b1    = (const float*)d_in[3];
    const float* g1    = (const float*)d_in[4];
    const float* bt1   = (const float*)d_in[5];
    const float* w_off = (const float*)d_in[6];
    const float* b_off = (const float*)d_in[7];
    const float* w_mod = (const float*)d_in[8];
    const float* b_mod = (const float*)d_in[9];
    const float* w_d   = (const float*)d_in[10];
    const float* b_d   = (const float*)d_in[11];
    const float* g2    = (const float*)d_in[12];
    const float* bt2   = (const float*)d_in[13];
    const float* w_ds  = (const float*)d_in[14];
    const float* b_ds  = (const float*)d_in[15];
    const float* g3    = (const float*)d_in[16];
    const float* bt3   = (const float*)d_in[17];

    float *xt, *y1h, *d2, *res, *off, *msk, *col, *st, *ps, *pq;
    float *w1p, *wdp, *wop, *wds, *bp;
    cudaGetSymbolAddress((void**)&xt,  g_xt);
    cudaGetSymbolAddress((void**)&y1h, g_y1h);
    cudaGetSymbolAddress((void**)&d2,  g_d2);
    cudaGetSymbolAddress((void**)&res, g_res);
    cudaGetSymbolAddress((void**)&off, g_off);
    cudaGetSymbolAddress((void**)&msk, g_mask);
    cudaGetSymbolAddress((void**)&col, g_col);
    cudaGetSymbolAddress((void**)&st,  g_stats);
    cudaGetSymbolAddress((void**)&ps,  g_ps);
    cudaGetSymbolAddress((void**)&pq,  g_pq);
    cudaGetSymbolAddress((void**)&w1p, g_w1p);
    cudaGetSymbolAddress((void**)&wdp, g_wdp);
    cudaGetSymbolAddress((void**)&wop, g_wop);
    cudaGetSymbolAddress((void**)&wds, g_wds);
    cudaGetSymbolAddress((void**)&bp,  g_bp);

    const int SM128 = 3 * (128*36 + 128*36) * 4;   // 110592
    const int SM32  = 3 * (32*36  + 128*36) * 4;   // 69120
    cudaFuncSetAttribute(gemm_conv1,  cudaFuncAttributeMaxDynamicSharedMemorySize, SM128);
    cudaFuncSetAttribute(gemm_dual,   cudaFuncAttributeMaxDynamicSharedMemorySize, SM128);
    cudaFuncSetAttribute(gemm_offmod, cudaFuncAttributeMaxDynamicSharedMemorySize, SM32);

    // 0) merged prep: NHWC x, all weight permutes/rounds
    prep_all<<<13344, 256>>>(x, xt, w1, w1p, w_d, wdp,
                             w_off, w_mod, b_off, b_mod, wop, bp, w_ds, wds);
    // 1) conv1: implicit 3x3 GEMM -> y1h NHWC raw + fused stats partials
    gemm_conv1<<<dim3(32, 2, BN), 128, SM128>>>(w1p, xt, b1, y1h, ps, pq);
    bn_combine<<<1, 256>>>(ps, pq, st);
    // 2) BN1 + ReLU + round, in place
    bn_relu_nhwc<<<(int)((size_t)BN*HWn*C/256), 256>>>(y1h, st, g1, bt1);
    // 3) offsets + modulation
    gemm_offmod<<<dim3(32, 1, BN), 128, SM32>>>(wop, y1h, bp, off, msk);
    // 4) bilinear gather -> col [b][pix][k]
    deform_sample<<<dim3(HWn, BN), 288>>>(y1h, off, msk, col);
    // 5) deform GEMM + 1x1 shortcut, grid-merged (co-scheduled)
    gemm_dual<<<dim3(32, 4, BN), 128, SM128>>>(
        wdp, col, b_d, d2, ps + 65536, pq + 65536,
        wds, xt,  b_ds, res, ps + 2*65536, pq + 2*65536);
    bn_combine_pair<<<2, 256>>>(ps, pq, st);
    // 6) fused BN2 + BN3 + add + ReLU (vectorized)
    final_fuse<<<BN*C*HWn/1024, 256>>>(d2, res, st, g2, bt2, g3, bt3, (float*)d_out);
}